// round 1
// baseline (speedup 1.0000x reference)
#include <cuda_runtime.h>
#include <math.h>

// Problem constants (fixed by reference setup_inputs)
#define BB 2
#define SS 4096
#define DD 1024
#define HH 16
#define DH 64
#define WW 256
#define NB 16          // SS / WW
#define MM (BB * SS)   // 8192 rows for all GEMMs

// Device scratch (allocation-free rule: use __device__ globals)
__device__ float g_q[MM * DD];
__device__ float g_k[MM * DD];
__device__ float g_v[MM * DD];
__device__ float g_ao[MM * DD];

// ---------------------------------------------------------------------------
// GEMM: C[M,N] = A[M,K] * Bw[N,K]^T   with N=K=1024 (nn.Linear y = x @ W^T)
// 128x128 block tile, BK=16, 256 threads, 8x8 microtile per thread.
// ---------------------------------------------------------------------------
__global__ __launch_bounds__(256) void gemm128(const float* __restrict__ A,
                                               const float* __restrict__ Bw,
                                               float* __restrict__ C) {
    __shared__ float As[16][132];
    __shared__ float Bs[16][132];

    const int bm = blockIdx.y << 7;
    const int bn = blockIdx.x << 7;
    const int t  = threadIdx.x;
    const int tx = t & 15;
    const int ty = t >> 4;

    // load indexing: thread owns rows m and m+64, one float4 (4 k-values) each
    const int m  = t >> 2;          // 0..63
    const int kq = (t & 3) << 2;    // 0,4,8,12

    float acc[8][8];
#pragma unroll
    for (int i = 0; i < 8; i++)
#pragma unroll
        for (int j = 0; j < 8; j++) acc[i][j] = 0.f;

    const float* Ag0 = A  + (size_t)(bm + m)      * DD + kq;
    const float* Ag1 = A  + (size_t)(bm + m + 64) * DD + kq;
    const float* Bg0 = Bw + (size_t)(bn + m)      * DD + kq;
    const float* Bg1 = Bw + (size_t)(bn + m + 64) * DD + kq;

    for (int k0 = 0; k0 < DD; k0 += 16) {
        float4 a0 = *(const float4*)(Ag0 + k0);
        float4 a1 = *(const float4*)(Ag1 + k0);
        float4 b0 = *(const float4*)(Bg0 + k0);
        float4 b1 = *(const float4*)(Bg1 + k0);

        As[kq + 0][m] = a0.x; As[kq + 1][m] = a0.y;
        As[kq + 2][m] = a0.z; As[kq + 3][m] = a0.w;
        As[kq + 0][m + 64] = a1.x; As[kq + 1][m + 64] = a1.y;
        As[kq + 2][m + 64] = a1.z; As[kq + 3][m + 64] = a1.w;
        Bs[kq + 0][m] = b0.x; Bs[kq + 1][m] = b0.y;
        Bs[kq + 2][m] = b0.z; Bs[kq + 3][m] = b0.w;
        Bs[kq + 0][m + 64] = b1.x; Bs[kq + 1][m + 64] = b1.y;
        Bs[kq + 2][m + 64] = b1.z; Bs[kq + 3][m + 64] = b1.w;

        __syncthreads();

#pragma unroll
        for (int kk = 0; kk < 16; kk++) {
            float4 a_0 = *(const float4*)&As[kk][ty << 3];
            float4 a_1 = *(const float4*)&As[kk][(ty << 3) + 4];
            float4 b_0 = *(const float4*)&Bs[kk][tx << 3];
            float4 b_1 = *(const float4*)&Bs[kk][(tx << 3) + 4];
            float ar[8] = {a_0.x, a_0.y, a_0.z, a_0.w, a_1.x, a_1.y, a_1.z, a_1.w};
            float br[8] = {b_0.x, b_0.y, b_0.z, b_0.w, b_1.x, b_1.y, b_1.z, b_1.w};
#pragma unroll
            for (int i = 0; i < 8; i++)
#pragma unroll
                for (int j = 0; j < 8; j++)
                    acc[i][j] = fmaf(ar[i], br[j], acc[i][j]);
        }
        __syncthreads();
    }

#pragma unroll
    for (int i = 0; i < 8; i++) {
        float* crow = C + (size_t)(bm + (ty << 3) + i) * DD + bn + (tx << 3);
        float4 v0 = make_float4(acc[i][0], acc[i][1], acc[i][2], acc[i][3]);
        float4 v1 = make_float4(acc[i][4], acc[i][5], acc[i][6], acc[i][7]);
        ((float4*)crow)[0] = v0;
        ((float4*)crow)[1] = v1;
    }
}

// ---------------------------------------------------------------------------
// Sliding-window attention.
// Grid: (nb, H, B). Block: 256 threads, one query row per thread.
// Each query i attends keys [max(0, i-W+1), i]; CTA window is the 2W keys
// [(j-1)*W, (j+1)*W). Online (flash) softmax; K/V streamed through smem in
// chunks of 64 keys (broadcast LDS reads → conflict-free).
// ---------------------------------------------------------------------------
__global__ __launch_bounds__(256, 1) void swa_kernel(const float* __restrict__ Q,
                                                     const float* __restrict__ Kg,
                                                     const float* __restrict__ Vg,
                                                     float* __restrict__ O) {
    const int j = blockIdx.x;
    const int h = blockIdx.y;
    const int b = blockIdx.z;
    const int t = threadIdx.x;          // query within block: 0..255
    const int i = j * WW + t;           // global query position

    __shared__ float Ks[64][68];
    __shared__ float Vs[64][68];

    // load this thread's query row (pre-scaled by 1/sqrt(Dh))
    float qr[DH];
    {
        const float* qrow = Q + ((size_t)(b * SS + i)) * DD + h * DH;
#pragma unroll
        for (int d = 0; d < DH; d += 4) {
            float4 qv = *(const float4*)(qrow + d);
            qr[d + 0] = qv.x * 0.125f;
            qr[d + 1] = qv.y * 0.125f;
            qr[d + 2] = qv.z * 0.125f;
            qr[d + 3] = qv.w * 0.125f;
        }
    }

    float mrun = -INFINITY;
    float lrun = 0.f;
    float acc[DH];
#pragma unroll
    for (int d = 0; d < DH; d++) acc[d] = 0.f;

    const int kv0 = (j - 1) * WW;       // start of the 2W window (may be <0)

    for (int c = 0; c < 8; c++) {
        const int kbase = kv0 + c * 64;
        if (kbase + 63 < 0) continue;   // whole chunk before sequence start

        __syncthreads();
        // stage K,V chunk: 64 keys x 64 dims each; 1024 float4 slots, 4 iters
#pragma unroll
        for (int it = 0; it < 4; it++) {
            int idx = t + it * 256;          // 0..1023
            int row = idx >> 4;              // 0..63
            int c4  = (idx & 15) << 2;       // 0..60
            int kp  = kbase + row;
            float4 kv = make_float4(0.f, 0.f, 0.f, 0.f);
            float4 vv = make_float4(0.f, 0.f, 0.f, 0.f);
            if (kp >= 0) {
                const size_t roff = ((size_t)(b * SS + kp)) * DD + h * DH + c4;
                kv = *(const float4*)(Kg + roff);
                vv = *(const float4*)(Vg + roff);
            }
            *(float4*)&Ks[row][c4] = kv;
            *(float4*)&Vs[row][c4] = vv;
        }
        __syncthreads();

        for (int kk = 0; kk < 64; kk++) {
            const int kp = kbase + kk;
            // dot(q, k) with 4 partial accumulators (broadcast smem reads)
            float s0 = 0.f, s1 = 0.f, s2 = 0.f, s3 = 0.f;
#pragma unroll
            for (int u = 0; u < 16; u++) {
                float4 kv = *(const float4*)&Ks[kk][u << 2];
                s0 = fmaf(qr[(u << 2) + 0], kv.x, s0);
                s1 = fmaf(qr[(u << 2) + 1], kv.y, s1);
                s2 = fmaf(qr[(u << 2) + 2], kv.z, s2);
                s3 = fmaf(qr[(u << 2) + 3], kv.w, s3);
            }
            float s = (s0 + s1) + (s2 + s3);

            const bool valid = (kp >= 0) && (kp <= i) && (kp >= i - (WW - 1));
            if (valid) {
                if (s > mrun) {
                    float corr = __expf(mrun - s);   // 0 when mrun = -inf
                    lrun *= corr;
#pragma unroll
                    for (int d = 0; d < DH; d++) acc[d] *= corr;
                    mrun = s;
                }
                float p = __expf(s - mrun);
                lrun += p;
#pragma unroll
                for (int u = 0; u < 16; u++) {
                    float4 vv = *(const float4*)&Vs[kk][u << 2];
                    acc[(u << 2) + 0] = fmaf(p, vv.x, acc[(u << 2) + 0]);
                    acc[(u << 2) + 1] = fmaf(p, vv.y, acc[(u << 2) + 1]);
                    acc[(u << 2) + 2] = fmaf(p, vv.z, acc[(u << 2) + 2]);
                    acc[(u << 2) + 3] = fmaf(p, vv.w, acc[(u << 2) + 3]);
                }
            }
        }
    }

    const float inv = 1.f / lrun;       // key kp=i is always valid → lrun > 0
    float* orow = O + ((size_t)(b * SS + i)) * DD + h * DH;
#pragma unroll
    for (int d = 0; d < DH; d += 4) {
        float4 ov = make_float4(acc[d] * inv, acc[d + 1] * inv,
                                acc[d + 2] * inv, acc[d + 3] * inv);
        *(float4*)(orow + d) = ov;
    }
}

// ---------------------------------------------------------------------------
extern "C" void kernel_launch(void* const* d_in, const int* in_sizes, int n_in,
                              void* d_out, int out_size) {
    const float* x  = (const float*)d_in[0];
    const float* wq = (const float*)d_in[1];
    const float* wk = (const float*)d_in[2];
    const float* wv = (const float*)d_in[3];
    const float* wo = (const float*)d_in[4];
    float* out = (float*)d_out;

    float *q, *k, *v, *ao;
    cudaGetSymbolAddress((void**)&q,  g_q);
    cudaGetSymbolAddress((void**)&k,  g_k);
    cudaGetSymbolAddress((void**)&v,  g_v);
    cudaGetSymbolAddress((void**)&ao, g_ao);

    dim3 gg(DD / 128, MM / 128);   // (8, 64)
    gemm128<<<gg, 256>>>(x, wq, q);
    gemm128<<<gg, 256>>>(x, wk, k);
    gemm128<<<gg, 256>>>(x, wv, v);

    dim3 ga(NB, HH, BB);           // (16, 16, 2)
    swa_kernel<<<ga, 256>>>(q, k, v, ao);

    gemm128<<<gg, 256>>>(ao, wo, out);
}

// round 3
// speedup vs baseline: 1.7819x; 1.7819x over previous
#include <cuda_runtime.h>
#include <cuda_bf16.h>
#include <math.h>
#include <stdint.h>

#define BB 2
#define SS 4096
#define DD 1024
#define HH 16
#define DH 64
#define WW 256
#define NB 16
#define MM (BB * SS)

// ---------------- device scratch (allocation-free rule) ----------------
__device__ float g_q[MM * DD];
__device__ float g_k[MM * DD];
__device__ float g_v[MM * DD];
__device__ float g_ao[MM * DD];
__device__ __nv_bfloat16 g_xh[MM * DD];
__device__ __nv_bfloat16 g_xl[MM * DD];
__device__ __nv_bfloat16 g_aoh[MM * DD];
__device__ __nv_bfloat16 g_aol[MM * DD];
__device__ __nv_bfloat16 g_wh[4][DD * DD];
__device__ __nv_bfloat16 g_wl[4][DD * DD];

// ---------------- family-portable PTX helpers (sm_80-class) ----------------
__device__ __forceinline__ uint32_t smem_u32(const void* p) {
    uint32_t a;
    asm("{ .reg .u64 t; cvta.to.shared.u64 t, %1; cvt.u32.u64 %0, t; }"
        : "=r"(a) : "l"(p));
    return a;
}

#define LDSM4(r0, r1, r2, r3, addr)                                            \
    asm volatile("ldmatrix.sync.aligned.m8n8.x4.shared.b16 {%0,%1,%2,%3}, [%4];" \
                 : "=r"(r0), "=r"(r1), "=r"(r2), "=r"(r3) : "r"(addr))

#define MMA16816(d, a, b)                                                      \
    asm volatile(                                                              \
        "mma.sync.aligned.m16n8k16.row.col.f32.bf16.bf16.f32 "                 \
        "{%0,%1,%2,%3},{%4,%5,%6,%7},{%8,%9},{%0,%1,%2,%3};"                   \
        : "+f"((d)[0]), "+f"((d)[1]), "+f"((d)[2]), "+f"((d)[3])               \
        : "r"((a)[0]), "r"((a)[1]), "r"((a)[2]), "r"((a)[3]),                  \
          "r"((b)[0]), "r"((b)[1]))

#define CPASYNC16(dst, src)                                                    \
    asm volatile("cp.async.cg.shared.global [%0], [%1], 16;"                   \
                 :: "r"(dst), "l"(src))
#define CPCOMMIT() asm volatile("cp.async.commit_group;" ::: "memory")
#define CPWAIT0()  asm volatile("cp.async.wait_group 0;" ::: "memory")

// smem geometry: row pitch 80 B (40 bf16). gcd(5,8)=1 -> the 8 16B-groups of
// any 8 consecutive rows land in 8 distinct bank-groups: ldmatrix conflict-free.
#define PITCH 80
#define TILE_B (128 * PITCH)   // 10240 B per 128x32 bf16 tile
#define STAGE_B (4 * TILE_B)   // Ah, Al, Bh, Bl
#define NSTAGE_K 32            // DD / 32

// ---------------------------------------------------------------------------
// fp32 -> bf16 (hi, lo) split:  x = hi + lo + O(2^-18 x)
// ---------------------------------------------------------------------------
__global__ __launch_bounds__(256) void split_bf16(const float* __restrict__ s,
                                                  __nv_bfloat16* __restrict__ hi,
                                                  __nv_bfloat16* __restrict__ lo,
                                                  int n) {
    int i = (blockIdx.x * 256 + threadIdx.x) * 4;
    if (i >= n) return;
    float4 v = *(const float4*)(s + i);
    float f[4] = {v.x, v.y, v.z, v.w};
    __nv_bfloat16 h[4], l[4];
#pragma unroll
    for (int j = 0; j < 4; j++) {
        h[j] = __float2bfloat16(f[j]);
        l[j] = __float2bfloat16(f[j] - __bfloat162float(h[j]));
    }
    *(__nv_bfloat162*)(hi + i)     = __halves2bfloat162(h[0], h[1]);
    *(__nv_bfloat162*)(hi + i + 2) = __halves2bfloat162(h[2], h[3]);
    *(__nv_bfloat162*)(lo + i)     = __halves2bfloat162(l[0], l[1]);
    *(__nv_bfloat162*)(lo + i + 2) = __halves2bfloat162(l[2], l[3]);
}

// ---------------------------------------------------------------------------
// Tensor-core GEMM: C[M,N] = (Ah+Al)[M,K] * (Wh+Wl)[N,K]^T, 3-term bf16 split.
// 128x128 block tile, BK=32, 256 threads = 8 warps (2m x 4n), 64x32 warp tile,
// mma.sync.m16n8k16, cp.async double-buffered smem.
// ---------------------------------------------------------------------------
extern __shared__ char dynsm[];

__global__ __launch_bounds__(256, 2)
void tgemm(const __nv_bfloat16* __restrict__ Ah, const __nv_bfloat16* __restrict__ Al,
           const __nv_bfloat16* __restrict__ Wh, const __nv_bfloat16* __restrict__ Wl,
           float* __restrict__ C) {
    const int t = threadIdx.x;
    const int lane = t & 31;
    const int wid = t >> 5;
    const int warp_m = wid >> 2;   // 0..1
    const int warp_n = wid & 3;    // 0..3
    const int bn = blockIdx.x << 7, bm = blockIdx.y << 7;

    const uint32_t sb = smem_u32(dynsm);

    // global sources for the 4 staged tiles
    const __nv_bfloat16* gsrc[4] = {
        Ah + (size_t)bm * DD, Al + (size_t)bm * DD,
        Wh + (size_t)bn * DD, Wl + (size_t)bn * DD};

    // cp.async mapping: 512 16B-chunks per tile; thread does 2 per tile
    const int r_ld = t >> 2;            // 0..63 (and +64)
    const int c_ld = (t & 3);           // 16B chunk within 64B row

    // ldmatrix per-lane offsets
    const uint32_t aOff = (uint32_t)((warp_m * 64 + (lane & 15)) * PITCH +
                                     ((lane >> 4) & 1) * 16);
    const uint32_t bOff = (uint32_t)(warp_n * 32 * PITCH +
                                     ((lane & 7) + ((lane >> 4) << 3)) * PITCH +
                                     ((lane >> 3) & 1) * 16);

    float acc[4][4][4];
#pragma unroll
    for (int i = 0; i < 4; i++)
#pragma unroll
        for (int j = 0; j < 4; j++)
#pragma unroll
            for (int r = 0; r < 4; r++) acc[i][j][r] = 0.f;

    // ---- prologue: stage 0 ----
#pragma unroll
    for (int tile = 0; tile < 4; tile++) {
#pragma unroll
        for (int h = 0; h < 2; h++) {
            int row = r_ld + h * 64;
            uint32_t dst = sb + tile * TILE_B + row * PITCH + c_ld * 16;
            const void* src = gsrc[tile] + (size_t)row * DD + c_ld * 8;
            CPASYNC16(dst, src);
        }
    }
    CPCOMMIT();

    for (int s = 0; s < NSTAGE_K; s++) {
        CPWAIT0();
        __syncthreads();

        if (s + 1 < NSTAGE_K) {
            const int k0 = (s + 1) * 32;
            const uint32_t stb = sb + ((s + 1) & 1) * STAGE_B;
#pragma unroll
            for (int tile = 0; tile < 4; tile++) {
#pragma unroll
                for (int h = 0; h < 2; h++) {
                    int row = r_ld + h * 64;
                    uint32_t dst = stb + tile * TILE_B + row * PITCH + c_ld * 16;
                    const void* src = gsrc[tile] + (size_t)row * DD + k0 + c_ld * 8;
                    CPASYNC16(dst, src);
                }
            }
            CPCOMMIT();
        }

        const uint32_t cb = sb + (s & 1) * STAGE_B;
        const uint32_t sAh = cb,            sAl = cb + TILE_B;
        const uint32_t sBh = cb + 2 * TILE_B, sBl = cb + 3 * TILE_B;

#pragma unroll
        for (int ks = 0; ks < 2; ks++) {
            const uint32_t kb = ks * 32;   // 16 bf16 = 32 bytes
            uint32_t bh[8], bl[8];
            LDSM4(bh[0], bh[1], bh[2], bh[3], sBh + bOff + kb);
            LDSM4(bh[4], bh[5], bh[6], bh[7], sBh + bOff + 16 * PITCH + kb);
            LDSM4(bl[0], bl[1], bl[2], bl[3], sBl + bOff + kb);
            LDSM4(bl[4], bl[5], bl[6], bl[7], sBl + bOff + 16 * PITCH + kb);
#pragma unroll
            for (int mf = 0; mf < 4; mf++) {
                uint32_t ah[4], al[4];
                LDSM4(ah[0], ah[1], ah[2], ah[3], sAh + aOff + mf * 16 * PITCH + kb);
                LDSM4(al[0], al[1], al[2], al[3], sAl + aOff + mf * 16 * PITCH + kb);
#pragma unroll
                for (int nf = 0; nf < 4; nf++) {
                    MMA16816(acc[mf][nf], ah, &bh[nf * 2]);
                    MMA16816(acc[mf][nf], ah, &bl[nf * 2]);
                    MMA16816(acc[mf][nf], al, &bh[nf * 2]);
                }
            }
        }
    }

    // ---- epilogue: fragment -> global (float2 stores) ----
#pragma unroll
    for (int mf = 0; mf < 4; mf++) {
        const int r0 = bm + warp_m * 64 + mf * 16 + (lane >> 2);
#pragma unroll
        for (int nf = 0; nf < 4; nf++) {
            const int cn = bn + warp_n * 32 + nf * 8 + (lane & 3) * 2;
            *(float2*)&C[(size_t)r0 * DD + cn] =
                make_float2(acc[mf][nf][0], acc[mf][nf][1]);
            *(float2*)&C[(size_t)(r0 + 8) * DD + cn] =
                make_float2(acc[mf][nf][2], acc[mf][nf][3]);
        }
    }
}

// ---------------------------------------------------------------------------
// Sliding-window attention (unchanged — fp32, flash-style).
// ---------------------------------------------------------------------------
__global__ __launch_bounds__(256, 1) void swa_kernel(const float* __restrict__ Q,
                                                     const float* __restrict__ Kg,
                                                     const float* __restrict__ Vg,
                                                     float* __restrict__ O) {
    const int j = blockIdx.x;
    const int h = blockIdx.y;
    const int b = blockIdx.z;
    const int t = threadIdx.x;
    const int i = j * WW + t;

    __shared__ float Ks[64][68];
    __shared__ float Vs[64][68];

    float qr[DH];
    {
        const float* qrow = Q + ((size_t)(b * SS + i)) * DD + h * DH;
#pragma unroll
        for (int d = 0; d < DH; d += 4) {
            float4 qv = *(const float4*)(qrow + d);
            qr[d + 0] = qv.x * 0.125f;
            qr[d + 1] = qv.y * 0.125f;
            qr[d + 2] = qv.z * 0.125f;
            qr[d + 3] = qv.w * 0.125f;
        }
    }

    float mrun = -INFINITY;
    float lrun = 0.f;
    float acc[DH];
#pragma unroll
    for (int d = 0; d < DH; d++) acc[d] = 0.f;

    const int kv0 = (j - 1) * WW;

    for (int c = 0; c < 8; c++) {
        const int kbase = kv0 + c * 64;
        if (kbase + 63 < 0) continue;

        __syncthreads();
#pragma unroll
        for (int it = 0; it < 4; it++) {
            int idx = t + it * 256;
            int row = idx >> 4;
            int c4 = (idx & 15) << 2;
            int kp = kbase + row;
            float4 kv = make_float4(0.f, 0.f, 0.f, 0.f);
            float4 vv = make_float4(0.f, 0.f, 0.f, 0.f);
            if (kp >= 0) {
                const size_t roff = ((size_t)(b * SS + kp)) * DD + h * DH + c4;
                kv = *(const float4*)(Kg + roff);
                vv = *(const float4*)(Vg + roff);
            }
            *(float4*)&Ks[row][c4] = kv;
            *(float4*)&Vs[row][c4] = vv;
        }
        __syncthreads();

        for (int kk = 0; kk < 64; kk++) {
            const int kp = kbase + kk;
            float s0 = 0.f, s1 = 0.f, s2 = 0.f, s3 = 0.f;
#pragma unroll
            for (int u = 0; u < 16; u++) {
                float4 kv = *(const float4*)&Ks[kk][u << 2];
                s0 = fmaf(qr[(u << 2) + 0], kv.x, s0);
                s1 = fmaf(qr[(u << 2) + 1], kv.y, s1);
                s2 = fmaf(qr[(u << 2) + 2], kv.z, s2);
                s3 = fmaf(qr[(u << 2) + 3], kv.w, s3);
            }
            float s = (s0 + s1) + (s2 + s3);

            const bool valid = (kp >= 0) && (kp <= i) && (kp >= i - (WW - 1));
            if (valid) {
                if (s > mrun) {
                    float corr = __expf(mrun - s);
                    lrun *= corr;
#pragma unroll
                    for (int d = 0; d < DH; d++) acc[d] *= corr;
                    mrun = s;
                }
                float p = __expf(s - mrun);
                lrun += p;
#pragma unroll
                for (int u = 0; u < 16; u++) {
                    float4 vv = *(const float4*)&Vs[kk][u << 2];
                    acc[(u << 2) + 0] = fmaf(p, vv.x, acc[(u << 2) + 0]);
                    acc[(u << 2) + 1] = fmaf(p, vv.y, acc[(u << 2) + 1]);
                    acc[(u << 2) + 2] = fmaf(p, vv.z, acc[(u << 2) + 2]);
                    acc[(u << 2) + 3] = fmaf(p, vv.w, acc[(u << 2) + 3]);
                }
            }
        }
    }

    const float inv = 1.f / lrun;
    float* orow = O + ((size_t)(b * SS + i)) * DD + h * DH;
#pragma unroll
    for (int d = 0; d < DH; d += 4) {
        float4 ov = make_float4(acc[d] * inv, acc[d + 1] * inv,
                                acc[d + 2] * inv, acc[d + 3] * inv);
        *(float4*)(orow + d) = ov;
    }
}

// ---------------------------------------------------------------------------
extern "C" void kernel_launch(void* const* d_in, const int* in_sizes, int n_in,
                              void* d_out, int out_size) {
    const float* x  = (const float*)d_in[0];
    const float* w[4] = {(const float*)d_in[1], (const float*)d_in[2],
                         (const float*)d_in[3], (const float*)d_in[4]};
    float* out = (float*)d_out;

    float *q, *k, *v, *ao;
    cudaGetSymbolAddress((void**)&q,  g_q);
    cudaGetSymbolAddress((void**)&k,  g_k);
    cudaGetSymbolAddress((void**)&v,  g_v);
    cudaGetSymbolAddress((void**)&ao, g_ao);
    __nv_bfloat16 *xh, *xl, *aoh, *aol, *wh, *wl;
    cudaGetSymbolAddress((void**)&xh,  g_xh);
    cudaGetSymbolAddress((void**)&xl,  g_xl);
    cudaGetSymbolAddress((void**)&aoh, g_aoh);
    cudaGetSymbolAddress((void**)&aol, g_aol);
    cudaGetSymbolAddress((void**)&wh,  g_wh);
    cudaGetSymbolAddress((void**)&wl,  g_wl);

    const int DYNSM = 2 * STAGE_B;   // 81920 B
    cudaFuncSetAttribute(tgemm, cudaFuncAttributeMaxDynamicSharedMemorySize, DYNSM);

    split_bf16<<<(MM * DD) / 1024, 256>>>(x, xh, xl, MM * DD);
    for (int i = 0; i < 4; i++)
        split_bf16<<<(DD * DD) / 1024, 256>>>(w[i], wh + (size_t)i * DD * DD,
                                              wl + (size_t)i * DD * DD, DD * DD);

    dim3 gg(DD / 128, MM / 128);  // (8, 64)
    tgemm<<<gg, 256, DYNSM>>>(xh, xl, wh + 0 * (size_t)DD * DD, wl + 0 * (size_t)DD * DD, q);
    tgemm<<<gg, 256, DYNSM>>>(xh, xl, wh + 1 * (size_t)DD * DD, wl + 1 * (size_t)DD * DD, k);
    tgemm<<<gg, 256, DYNSM>>>(xh, xl, wh + 2 * (size_t)DD * DD, wl + 2 * (size_t)DD * DD, v);

    dim3 ga(NB, HH, BB);
    swa_kernel<<<ga, 256>>>(q, k, v, ao);

    split_bf16<<<(MM * DD) / 1024, 256>>>(ao, aoh, aol, MM * DD);
    tgemm<<<gg, 256, DYNSM>>>(aoh, aol, wh + 3 * (size_t)DD * DD, wl + 3 * (size_t)DD * DD, out);
}

// round 4
// speedup vs baseline: 3.0495x; 1.7114x over previous
#include <cuda_runtime.h>
#include <cuda_bf16.h>
#include <math.h>
#include <stdint.h>

#define BB 2
#define SS 4096
#define DD 1024
#define HH 16
#define DH 64
#define WW 256
#define MM (BB * SS)

// ---------------- device scratch (allocation-free rule) ----------------
__device__ __nv_bfloat16 g_xh[MM * DD];
__device__ __nv_bfloat16 g_xl[MM * DD];
__device__ __nv_bfloat16 g_wh[4][DD * DD];
__device__ __nv_bfloat16 g_wl[4][DD * DD];
__device__ __nv_bfloat16 g_qh[MM * DD];
__device__ __nv_bfloat16 g_ql[MM * DD];
__device__ __nv_bfloat16 g_kh[MM * DD];
__device__ __nv_bfloat16 g_kl[MM * DD];
__device__ __nv_bfloat16 g_vh[MM * DD];
__device__ __nv_bfloat16 g_vl[MM * DD];
__device__ __nv_bfloat16 g_aoh[MM * DD];
__device__ __nv_bfloat16 g_aol[MM * DD];

// ---------------- family-portable PTX helpers ----------------
__device__ __forceinline__ uint32_t smem_u32(const void* p) {
    uint32_t a;
    asm("{ .reg .u64 t; cvta.to.shared.u64 t, %1; cvt.u32.u64 %0, t; }"
        : "=r"(a) : "l"(p));
    return a;
}

#define LDSM4(r0, r1, r2, r3, addr)                                              \
    asm volatile("ldmatrix.sync.aligned.m8n8.x4.shared.b16 {%0,%1,%2,%3}, [%4];"  \
                 : "=r"(r0), "=r"(r1), "=r"(r2), "=r"(r3) : "r"(addr))
#define LDSM4T(r0, r1, r2, r3, addr)                                             \
    asm volatile("ldmatrix.sync.aligned.m8n8.x4.trans.shared.b16 {%0,%1,%2,%3}, [%4];" \
                 : "=r"(r0), "=r"(r1), "=r"(r2), "=r"(r3) : "r"(addr))

#define MMA16816(d, a, b)                                                        \
    asm volatile(                                                                \
        "mma.sync.aligned.m16n8k16.row.col.f32.bf16.bf16.f32 "                   \
        "{%0,%1,%2,%3},{%4,%5,%6,%7},{%8,%9},{%0,%1,%2,%3};"                     \
        : "+f"((d)[0]), "+f"((d)[1]), "+f"((d)[2]), "+f"((d)[3])                 \
        : "r"((a)[0]), "r"((a)[1]), "r"((a)[2]), "r"((a)[3]),                    \
          "r"((b)[0]), "r"((b)[1]))

#define CPASYNC16(dst, src)                                                      \
    asm volatile("cp.async.cg.shared.global [%0], [%1], 16;" :: "r"(dst), "l"(src))
#define CPASYNC16Z(dst, src, sz)                                                 \
    asm volatile("cp.async.cg.shared.global [%0], [%1], 16, %2;"                  \
                 :: "r"(dst), "l"(src), "r"(sz))
#define CPCOMMIT() asm volatile("cp.async.commit_group;" ::: "memory")
#define CPWAIT0()  asm volatile("cp.async.wait_group 0;" ::: "memory")
#define CPWAIT1()  asm volatile("cp.async.wait_group 1;" ::: "memory")

// bf16 hi/lo split of a float pair -> two packed bf16x2 regs
#define PSPLIT(ph, pl, va, vb)                                                   \
    {                                                                            \
        __nv_bfloat162 _h = __float22bfloat162_rn(make_float2((va), (vb)));      \
        float _ra = (va) - __bfloat162float(__low2bfloat16(_h));                 \
        float _rb = (vb) - __bfloat162float(__high2bfloat16(_h));                \
        __nv_bfloat162 _l = __float22bfloat162_rn(make_float2(_ra, _rb));        \
        (ph) = *(uint32_t*)&_h;                                                  \
        (pl) = *(uint32_t*)&_l;                                                  \
    }

// GEMM smem geometry (pitch 80 B: gcd(5,8)=1 -> conflict-free ldmatrix)
#define PITCH 80
#define TILE_B (128 * PITCH)
#define STAGE_B (4 * TILE_B)
#define NSTAGE_K 32

extern __shared__ char dynsm[];

// ---------------------------------------------------------------------------
// fp32 -> bf16 (hi, lo) split
// ---------------------------------------------------------------------------
__global__ __launch_bounds__(256) void split_bf16(const float* __restrict__ s,
                                                  __nv_bfloat16* __restrict__ hi,
                                                  __nv_bfloat16* __restrict__ lo,
                                                  int n) {
    int i = (blockIdx.x * 256 + threadIdx.x) * 4;
    if (i >= n) return;
    float4 v = *(const float4*)(s + i);
    float f[4] = {v.x, v.y, v.z, v.w};
    __nv_bfloat16 h[4], l[4];
#pragma unroll
    for (int j = 0; j < 4; j++) {
        h[j] = __float2bfloat16(f[j]);
        l[j] = __float2bfloat16(f[j] - __bfloat162float(h[j]));
    }
    *(__nv_bfloat162*)(hi + i)     = __halves2bfloat162(h[0], h[1]);
    *(__nv_bfloat162*)(hi + i + 2) = __halves2bfloat162(h[2], h[3]);
    *(__nv_bfloat162*)(lo + i)     = __halves2bfloat162(l[0], l[1]);
    *(__nv_bfloat162*)(lo + i + 2) = __halves2bfloat162(l[2], l[3]);
}

// ---------------------------------------------------------------------------
// Tensor-core GEMM (3-term bf16 split). Epilogue: fp32 store OR split-bf16
// store (with optional scale) when Ch != nullptr.
// ---------------------------------------------------------------------------
__global__ __launch_bounds__(256, 2)
void tgemm(const __nv_bfloat16* __restrict__ Ah, const __nv_bfloat16* __restrict__ Al,
           const __nv_bfloat16* __restrict__ Wh, const __nv_bfloat16* __restrict__ Wl,
           float* __restrict__ C, __nv_bfloat16* __restrict__ Ch,
           __nv_bfloat16* __restrict__ Cl, float scale) {
    const int t = threadIdx.x;
    const int lane = t & 31;
    const int wid = t >> 5;
    const int warp_m = wid >> 2;
    const int warp_n = wid & 3;
    const int bn = blockIdx.x << 7, bm = blockIdx.y << 7;

    const uint32_t sb = smem_u32(dynsm);

    const __nv_bfloat16* gsrc[4] = {
        Ah + (size_t)bm * DD, Al + (size_t)bm * DD,
        Wh + (size_t)bn * DD, Wl + (size_t)bn * DD};

    const int r_ld = t >> 2;
    const int c_ld = (t & 3);

    const uint32_t aOff = (uint32_t)((warp_m * 64 + (lane & 15)) * PITCH +
                                     ((lane >> 4) & 1) * 16);
    const uint32_t bOff = (uint32_t)(warp_n * 32 * PITCH +
                                     ((lane & 7) + ((lane >> 4) << 3)) * PITCH +
                                     ((lane >> 3) & 1) * 16);

    float acc[4][4][4];
#pragma unroll
    for (int i = 0; i < 4; i++)
#pragma unroll
        for (int j = 0; j < 4; j++)
#pragma unroll
            for (int r = 0; r < 4; r++) acc[i][j][r] = 0.f;

#pragma unroll
    for (int tile = 0; tile < 4; tile++)
#pragma unroll
        for (int h = 0; h < 2; h++) {
            int row = r_ld + h * 64;
            uint32_t dst = sb + tile * TILE_B + row * PITCH + c_ld * 16;
            const void* src = gsrc[tile] + (size_t)row * DD + c_ld * 8;
            CPASYNC16(dst, src);
        }
    CPCOMMIT();

    for (int s = 0; s < NSTAGE_K; s++) {
        CPWAIT0();
        __syncthreads();

        if (s + 1 < NSTAGE_K) {
            const int k0 = (s + 1) * 32;
            const uint32_t stb = sb + ((s + 1) & 1) * STAGE_B;
#pragma unroll
            for (int tile = 0; tile < 4; tile++)
#pragma unroll
                for (int h = 0; h < 2; h++) {
                    int row = r_ld + h * 64;
                    uint32_t dst = stb + tile * TILE_B + row * PITCH + c_ld * 16;
                    const void* src = gsrc[tile] + (size_t)row * DD + k0 + c_ld * 8;
                    CPASYNC16(dst, src);
                }
            CPCOMMIT();
        }

        const uint32_t cb = sb + (s & 1) * STAGE_B;
        const uint32_t sAh = cb,              sAl = cb + TILE_B;
        const uint32_t sBh = cb + 2 * TILE_B, sBl = cb + 3 * TILE_B;

#pragma unroll
        for (int ks = 0; ks < 2; ks++) {
            const uint32_t kb = ks * 32;
            uint32_t bh[8], bl[8];
            LDSM4(bh[0], bh[1], bh[2], bh[3], sBh + bOff + kb);
            LDSM4(bh[4], bh[5], bh[6], bh[7], sBh + bOff + 16 * PITCH + kb);
            LDSM4(bl[0], bl[1], bl[2], bl[3], sBl + bOff + kb);
            LDSM4(bl[4], bl[5], bl[6], bl[7], sBl + bOff + 16 * PITCH + kb);
#pragma unroll
            for (int mf = 0; mf < 4; mf++) {
                uint32_t ah[4], al[4];
                LDSM4(ah[0], ah[1], ah[2], ah[3], sAh + aOff + mf * 16 * PITCH + kb);
                LDSM4(al[0], al[1], al[2], al[3], sAl + aOff + mf * 16 * PITCH + kb);
#pragma unroll
                for (int nf = 0; nf < 4; nf++) {
                    MMA16816(acc[mf][nf], ah, &bh[nf * 2]);
                    MMA16816(acc[mf][nf], ah, &bl[nf * 2]);
                    MMA16816(acc[mf][nf], al, &bh[nf * 2]);
                }
            }
        }
    }

    if (Ch != nullptr) {
        // split-bf16 epilogue (optionally scaled)
#pragma unroll
        for (int mf = 0; mf < 4; mf++) {
            const int r0 = bm + warp_m * 64 + mf * 16 + (lane >> 2);
#pragma unroll
            for (int nf = 0; nf < 4; nf++) {
                const int cn = bn + warp_n * 32 + nf * 8 + (lane & 3) * 2;
#pragma unroll
                for (int hh = 0; hh < 2; hh++) {
                    float v0 = acc[mf][nf][hh * 2 + 0] * scale;
                    float v1 = acc[mf][nf][hh * 2 + 1] * scale;
                    uint32_t ph, pl;
                    PSPLIT(ph, pl, v0, v1);
                    size_t off = (size_t)(r0 + hh * 8) * DD + cn;
                    *(uint32_t*)&Ch[off] = ph;
                    *(uint32_t*)&Cl[off] = pl;
                }
            }
        }
    } else {
#pragma unroll
        for (int mf = 0; mf < 4; mf++) {
            const int r0 = bm + warp_m * 64 + mf * 16 + (lane >> 2);
#pragma unroll
            for (int nf = 0; nf < 4; nf++) {
                const int cn = bn + warp_n * 32 + nf * 8 + (lane & 3) * 2;
                *(float2*)&C[(size_t)r0 * DD + cn] =
                    make_float2(acc[mf][nf][0], acc[mf][nf][1]);
                *(float2*)&C[(size_t)(r0 + 8) * DD + cn] =
                    make_float2(acc[mf][nf][2], acc[mf][nf][3]);
            }
        }
    }
}

// ---------------------------------------------------------------------------
// Tensor-core sliding-window flash attention.
// Grid (S/128, H, B) = (32,16,2). 256 thr = 8 warps x 16 q-rows.
// Key window: 6 chunks of 64 starting at kv0 = 128*jq - 256.
// smem: double-buffered [Kh|Kl|Vh|Vl] chunk tiles, 64 x 64 bf16, pitch 144.
// ---------------------------------------------------------------------------
#define APITCH 144
#define ATILE (64 * APITCH)    // 9216
#define ABUF  (4 * ATILE)      // 36864

__global__ __launch_bounds__(256, 1)
void swa_mma(const __nv_bfloat16* __restrict__ Qh, const __nv_bfloat16* __restrict__ Ql,
             const __nv_bfloat16* __restrict__ Kh, const __nv_bfloat16* __restrict__ Kl,
             const __nv_bfloat16* __restrict__ Vh, const __nv_bfloat16* __restrict__ Vl,
             __nv_bfloat16* __restrict__ Oh, __nv_bfloat16* __restrict__ Ol) {
    const int jq = blockIdx.x, h = blockIdx.y, b = blockIdx.z;
    const int t = threadIdx.x, lane = t & 31, wid = t >> 5;
    const int tq = wid * 16;
    const uint32_t sb = smem_u32(dynsm);
    const int kv0 = 128 * jq - 256;

    // ---- Q fragments from global (pre-scaled, pre-split) ----
    uint32_t qA[2][4][4];
    {
        const int r0 = 128 * jq + tq + (lane >> 2);
        const size_t rowb = (size_t)(b * SS + r0) * DD + h * DH + 2 * (lane & 3);
        const __nv_bfloat16* Qs[2] = {Qh, Ql};
#pragma unroll
        for (int term = 0; term < 2; term++)
#pragma unroll
            for (int kf = 0; kf < 4; kf++) {
                qA[term][kf][0] = *(const uint32_t*)(Qs[term] + rowb + kf * 16);
                qA[term][kf][1] = *(const uint32_t*)(Qs[term] + rowb + 8 * DD + kf * 16);
                qA[term][kf][2] = *(const uint32_t*)(Qs[term] + rowb + kf * 16 + 8);
                qA[term][kf][3] = *(const uint32_t*)(Qs[term] + rowb + 8 * DD + kf * 16 + 8);
            }
    }

    const __nv_bfloat16* srcs[4] = {Kh, Kl, Vh, Vl};
    auto load_chunk = [&](int c, int buf) {
        const int kbase = kv0 + 64 * c;
#pragma unroll
        for (int it = 0; it < 8; it++) {
            int idx = t + it * 256;
            int tensor = idx >> 9;
            int row = (idx >> 3) & 63;
            int dch = idx & 7;
            int kp = kbase + row;
            int ok = (kp >= 0) ? 16 : 0;
            int kpc = kp >= 0 ? kp : 0;
            uint32_t dst = sb + buf * ABUF + tensor * ATILE + row * APITCH + dch * 16;
            const void* src = srcs[tensor] + (size_t)(b * SS + kpc) * DD + h * DH + dch * 8;
            CPASYNC16Z(dst, src, ok);
        }
    };

    float o[8][4];
#pragma unroll
    for (int nf = 0; nf < 8; nf++)
#pragma unroll
        for (int r = 0; r < 4; r++) o[nf][r] = 0.f;
    float m0 = -1e30f, m1 = -1e30f, lp0 = 0.f, lp1 = 0.f;

    const int cmin = (tq + 1) >> 6;
    const int cmax = (tq + 271) >> 6;

    load_chunk(0, 0);
    CPCOMMIT();

    for (int c = 0; c < 6; c++) {
        if (c < 5) {
            load_chunk(c + 1, (c + 1) & 1);
            CPCOMMIT();
            CPWAIT1();
        } else {
            CPWAIT0();
        }
        __syncthreads();

        const int kbase = kv0 + 64 * c;
        if (c >= cmin && c <= cmax && kbase + 63 >= 0) {
            const uint32_t kvb = sb + (c & 1) * ABUF;

            // ---- S = Q K^T (3-term) ----
            float s[8][4];
#pragma unroll
            for (int nf = 0; nf < 8; nf++)
#pragma unroll
                for (int r = 0; r < 4; r++) s[nf][r] = 0.f;

#pragma unroll
            for (int kf = 0; kf < 4; kf++) {
#pragma unroll
                for (int kg = 0; kg < 4; kg++) {
                    uint32_t addr = kvb +
                        (kg * 16 + (lane & 7) + ((lane >> 4) << 3)) * APITCH +
                        ((lane >> 3) & 1) * 16 + kf * 32;
                    uint32_t bh[4], bl[4];
                    LDSM4(bh[0], bh[1], bh[2], bh[3], addr);
                    LDSM4(bl[0], bl[1], bl[2], bl[3], addr + ATILE);
                    MMA16816(s[2 * kg],     qA[0][kf], &bh[0]);
                    MMA16816(s[2 * kg],     qA[0][kf], &bl[0]);
                    MMA16816(s[2 * kg],     qA[1][kf], &bh[0]);
                    MMA16816(s[2 * kg + 1], qA[0][kf], &bh[2]);
                    MMA16816(s[2 * kg + 1], qA[0][kf], &bl[2]);
                    MMA16816(s[2 * kg + 1], qA[1][kf], &bh[2]);
                }
            }

            // ---- band mask: valid iff 0 <= q - key <= 255 ----
            {
                const int qg = 128 * jq + tq + (lane >> 2);
                const int d0 = qg - (kbase + 2 * (lane & 3));
#pragma unroll
                for (int nf = 0; nf < 8; nf++) {
                    int e = d0 - nf * 8;
                    s[nf][0] = ((unsigned)e <= 255u)       ? s[nf][0] : -1e30f;
                    s[nf][1] = ((unsigned)(e - 1) <= 255u) ? s[nf][1] : -1e30f;
                    s[nf][2] = ((unsigned)(e + 8) <= 255u) ? s[nf][2] : -1e30f;
                    s[nf][3] = ((unsigned)(e + 7) <= 255u) ? s[nf][3] : -1e30f;
                }
            }

            // ---- online softmax ----
            float mx0 = -1e30f, mx1 = -1e30f;
#pragma unroll
            for (int nf = 0; nf < 8; nf++) {
                mx0 = fmaxf(mx0, fmaxf(s[nf][0], s[nf][1]));
                mx1 = fmaxf(mx1, fmaxf(s[nf][2], s[nf][3]));
            }
            mx0 = fmaxf(mx0, __shfl_xor_sync(0xffffffffu, mx0, 1));
            mx0 = fmaxf(mx0, __shfl_xor_sync(0xffffffffu, mx0, 2));
            mx1 = fmaxf(mx1, __shfl_xor_sync(0xffffffffu, mx1, 1));
            mx1 = fmaxf(mx1, __shfl_xor_sync(0xffffffffu, mx1, 2));

            float mn0 = fmaxf(m0, mx0), mn1 = fmaxf(m1, mx1);
            float c0 = __expf(m0 - mn0), c1 = __expf(m1 - mn1);
            m0 = mn0; m1 = mn1;

            float ls0 = 0.f, ls1 = 0.f;
#pragma unroll
            for (int nf = 0; nf < 8; nf++) {
                s[nf][0] = __expf(s[nf][0] - mn0);
                s[nf][1] = __expf(s[nf][1] - mn0);
                s[nf][2] = __expf(s[nf][2] - mn1);
                s[nf][3] = __expf(s[nf][3] - mn1);
                ls0 += s[nf][0] + s[nf][1];
                ls1 += s[nf][2] + s[nf][3];
            }
            lp0 = lp0 * c0 + ls0;
            lp1 = lp1 * c1 + ls1;
#pragma unroll
            for (int nf = 0; nf < 8; nf++) {
                o[nf][0] *= c0; o[nf][1] *= c0;
                o[nf][2] *= c1; o[nf][3] *= c1;
            }

            // ---- O += P V (3-term) ----
#pragma unroll
            for (int kf = 0; kf < 4; kf++) {
                uint32_t pha[4], pla[4];
                PSPLIT(pha[0], pla[0], s[2 * kf][0], s[2 * kf][1]);
                PSPLIT(pha[1], pla[1], s[2 * kf][2], s[2 * kf][3]);
                PSPLIT(pha[2], pla[2], s[2 * kf + 1][0], s[2 * kf + 1][1]);
                PSPLIT(pha[3], pla[3], s[2 * kf + 1][2], s[2 * kf + 1][3]);
#pragma unroll
                for (int dg = 0; dg < 4; dg++) {
                    uint32_t vaddr = kvb + 2 * ATILE +
                        (kf * 16 + (lane & 15)) * APITCH + dg * 32 +
                        ((lane >> 4) & 1) * 16;
                    uint32_t vh4[4], vl4[4];
                    LDSM4T(vh4[0], vh4[1], vh4[2], vh4[3], vaddr);
                    LDSM4T(vl4[0], vl4[1], vl4[2], vl4[3], vaddr + ATILE);
                    MMA16816(o[2 * dg],     pha, &vh4[0]);
                    MMA16816(o[2 * dg],     pha, &vl4[0]);
                    MMA16816(o[2 * dg],     pla, &vh4[0]);
                    MMA16816(o[2 * dg + 1], pha, &vh4[2]);
                    MMA16816(o[2 * dg + 1], pha, &vl4[2]);
                    MMA16816(o[2 * dg + 1], pla, &vh4[2]);
                }
            }
        }
        __syncthreads();
    }

    // ---- finalize: normalize, split, store ----
    lp0 += __shfl_xor_sync(0xffffffffu, lp0, 1);
    lp0 += __shfl_xor_sync(0xffffffffu, lp0, 2);
    lp1 += __shfl_xor_sync(0xffffffffu, lp1, 1);
    lp1 += __shfl_xor_sync(0xffffffffu, lp1, 2);
    const float inv0 = 1.f / lp0, inv1 = 1.f / lp1;

    const int r0 = 128 * jq + tq + (lane >> 2);
    const size_t ob = (size_t)(b * SS + r0) * DD + h * DH + 2 * (lane & 3);
#pragma unroll
    for (int nf = 0; nf < 8; nf++) {
        float v0 = o[nf][0] * inv0, v1 = o[nf][1] * inv0;
        float v2 = o[nf][2] * inv1, v3 = o[nf][3] * inv1;
        uint32_t ph, pl;
        PSPLIT(ph, pl, v0, v1);
        *(uint32_t*)&Oh[ob + nf * 8] = ph;
        *(uint32_t*)&Ol[ob + nf * 8] = pl;
        PSPLIT(ph, pl, v2, v3);
        *(uint32_t*)&Oh[ob + 8 * DD + nf * 8] = ph;
        *(uint32_t*)&Ol[ob + 8 * DD + nf * 8] = pl;
    }
}

// ---------------------------------------------------------------------------
extern "C" void kernel_launch(void* const* d_in, const int* in_sizes, int n_in,
                              void* d_out, int out_size) {
    const float* x = (const float*)d_in[0];
    const float* w[4] = {(const float*)d_in[1], (const float*)d_in[2],
                         (const float*)d_in[3], (const float*)d_in[4]};
    float* out = (float*)d_out;

    __nv_bfloat16 *xh, *xl, *wh, *wl, *qh, *ql, *kh, *kl, *vh, *vl, *aoh, *aol;
    cudaGetSymbolAddress((void**)&xh, g_xh);
    cudaGetSymbolAddress((void**)&xl, g_xl);
    cudaGetSymbolAddress((void**)&wh, g_wh);
    cudaGetSymbolAddress((void**)&wl, g_wl);
    cudaGetSymbolAddress((void**)&qh, g_qh);
    cudaGetSymbolAddress((void**)&ql, g_ql);
    cudaGetSymbolAddress((void**)&kh, g_kh);
    cudaGetSymbolAddress((void**)&kl, g_kl);
    cudaGetSymbolAddress((void**)&vh, g_vh);
    cudaGetSymbolAddress((void**)&vl, g_vl);
    cudaGetSymbolAddress((void**)&aoh, g_aoh);
    cudaGetSymbolAddress((void**)&aol, g_aol);

    const int DYNSM_G = 2 * STAGE_B;
    const int DYNSM_A = 2 * ABUF;
    cudaFuncSetAttribute(tgemm, cudaFuncAttributeMaxDynamicSharedMemorySize, DYNSM_G);
    cudaFuncSetAttribute(swa_mma, cudaFuncAttributeMaxDynamicSharedMemorySize, DYNSM_A);

    split_bf16<<<(MM * DD) / 1024, 256>>>(x, xh, xl, MM * DD);
    for (int i = 0; i < 4; i++)
        split_bf16<<<(DD * DD) / 1024, 256>>>(w[i], wh + (size_t)i * DD * DD,
                                              wl + (size_t)i * DD * DD, DD * DD);

    dim3 gg(DD / 128, MM / 128);
    // Q projection pre-scaled by 1/sqrt(Dh) = 0.125
    tgemm<<<gg, 256, DYNSM_G>>>(xh, xl, wh + 0 * (size_t)DD * DD, wl + 0 * (size_t)DD * DD,
                                nullptr, qh, ql, 0.125f);
    tgemm<<<gg, 256, DYNSM_G>>>(xh, xl, wh + 1 * (size_t)DD * DD, wl + 1 * (size_t)DD * DD,
                                nullptr, kh, kl, 1.0f);
    tgemm<<<gg, 256, DYNSM_G>>>(xh, xl, wh + 2 * (size_t)DD * DD, wl + 2 * (size_t)DD * DD,
                                nullptr, vh, vl, 1.0f);

    dim3 ga(SS / 128, HH, BB);   // (32, 16, 2)
    swa_mma<<<ga, 256, DYNSM_A>>>(qh, ql, kh, kl, vh, vl, aoh, aol);

    tgemm<<<gg, 256, DYNSM_G>>>(aoh, aol, wh + 3 * (size_t)DD * DD, wl + 3 * (size_t)DD * DD,
                                out, nullptr, nullptr, 1.0f);
}

// round 5
// speedup vs baseline: 3.2414x; 1.0629x over previous
#include <cuda_runtime.h>
#include <cuda_bf16.h>
#include <math.h>
#include <stdint.h>

#define BB 2
#define SS 4096
#define DD 1024
#define HH 16
#define DH 64
#define WW 256
#define MM (BB * SS)

// ---------------- device scratch (allocation-free rule) ----------------
__device__ __nv_bfloat16 g_xh[MM * DD];
__device__ __nv_bfloat16 g_xl[MM * DD];
__device__ __nv_bfloat16 g_wh[4][DD * DD];
__device__ __nv_bfloat16 g_wl[4][DD * DD];
__device__ __nv_bfloat16 g_qh[MM * DD];
__device__ __nv_bfloat16 g_ql[MM * DD];
__device__ __nv_bfloat16 g_kh[MM * DD];
__device__ __nv_bfloat16 g_kl[MM * DD];
__device__ __nv_bfloat16 g_vh[MM * DD];
__device__ __nv_bfloat16 g_vl[MM * DD];
__device__ __nv_bfloat16 g_aoh[MM * DD];
__device__ __nv_bfloat16 g_aol[MM * DD];

// ---------------- family-portable PTX helpers ----------------
__device__ __forceinline__ uint32_t smem_u32(const void* p) {
    uint32_t a;
    asm("{ .reg .u64 t; cvta.to.shared.u64 t, %1; cvt.u32.u64 %0, t; }"
        : "=r"(a) : "l"(p));
    return a;
}

#define LDSM4(r0, r1, r2, r3, addr)                                              \
    asm volatile("ldmatrix.sync.aligned.m8n8.x4.shared.b16 {%0,%1,%2,%3}, [%4];"  \
                 : "=r"(r0), "=r"(r1), "=r"(r2), "=r"(r3) : "r"(addr))
#define LDSM4T(r0, r1, r2, r3, addr)                                             \
    asm volatile("ldmatrix.sync.aligned.m8n8.x4.trans.shared.b16 {%0,%1,%2,%3}, [%4];" \
                 : "=r"(r0), "=r"(r1), "=r"(r2), "=r"(r3) : "r"(addr))

#define MMA16816(d, a, b)                                                        \
    asm volatile(                                                                \
        "mma.sync.aligned.m16n8k16.row.col.f32.bf16.bf16.f32 "                   \
        "{%0,%1,%2,%3},{%4,%5,%6,%7},{%8,%9},{%0,%1,%2,%3};"                     \
        : "+f"((d)[0]), "+f"((d)[1]), "+f"((d)[2]), "+f"((d)[3])                 \
        : "r"((a)[0]), "r"((a)[1]), "r"((a)[2]), "r"((a)[3]),                    \
          "r"((b)[0]), "r"((b)[1]))

#define CPASYNC16(dst, src)                                                      \
    asm volatile("cp.async.cg.shared.global [%0], [%1], 16;" :: "r"(dst), "l"(src))
#define CPASYNC16Z(dst, src, sz)                                                 \
    asm volatile("cp.async.cg.shared.global [%0], [%1], 16, %2;"                  \
                 :: "r"(dst), "l"(src), "r"(sz))
#define CPCOMMIT() asm volatile("cp.async.commit_group;" ::: "memory")
#define CPWAIT0()  asm volatile("cp.async.wait_group 0;" ::: "memory")
#define CPWAIT1()  asm volatile("cp.async.wait_group 1;" ::: "memory")

// bf16 hi/lo split of a float pair -> two packed bf16x2 regs
#define PSPLIT(ph, pl, va, vb)                                                   \
    {                                                                            \
        __nv_bfloat162 _h = __float22bfloat162_rn(make_float2((va), (vb)));      \
        float _ra = (va) - __bfloat162float(__low2bfloat16(_h));                 \
        float _rb = (vb) - __bfloat162float(__high2bfloat16(_h));                \
        __nv_bfloat162 _l = __float22bfloat162_rn(make_float2(_ra, _rb));        \
        (ph) = *(uint32_t*)&_h;                                                  \
        (pl) = *(uint32_t*)&_l;                                                  \
    }

// GEMM smem geometry (pitch 80 B: gcd(5,8)=1 -> conflict-free ldmatrix)
#define PITCH 80
#define TILE_B (128 * PITCH)
#define STAGE_B (4 * TILE_B)
#define NSTAGE_K 32

extern __shared__ char dynsm[];

// ---------------------------------------------------------------------------
// fp32 -> bf16 (hi, lo) split
// ---------------------------------------------------------------------------
__global__ __launch_bounds__(256) void split_bf16(const float* __restrict__ s,
                                                  __nv_bfloat16* __restrict__ hi,
                                                  __nv_bfloat16* __restrict__ lo,
                                                  int n) {
    int i = (blockIdx.x * 256 + threadIdx.x) * 4;
    if (i >= n) return;
    float4 v = *(const float4*)(s + i);
    float f[4] = {v.x, v.y, v.z, v.w};
    __nv_bfloat16 h[4], l[4];
#pragma unroll
    for (int j = 0; j < 4; j++) {
        h[j] = __float2bfloat16(f[j]);
        l[j] = __float2bfloat16(f[j] - __bfloat162float(h[j]));
    }
    *(__nv_bfloat162*)(hi + i)     = __halves2bfloat162(h[0], h[1]);
    *(__nv_bfloat162*)(hi + i + 2) = __halves2bfloat162(h[2], h[3]);
    *(__nv_bfloat162*)(lo + i)     = __halves2bfloat162(l[0], l[1]);
    *(__nv_bfloat162*)(lo + i + 2) = __halves2bfloat162(l[2], l[3]);
}

// ---------------------------------------------------------------------------
// Tensor-core GEMM (3-term bf16 split), QKV-fused via blockIdx.z.
// W = Wh + z*DD*DD. Output: if Ch0 set, split-bf16 epilogue (per-z dest /
// scale), else fp32 into C.
// Mainloop: stage-hoisted B fragments, register-double-buffered A fragments,
// product-major MMA order.
// ---------------------------------------------------------------------------
__global__ __launch_bounds__(256, 2)
void tgemm(const __nv_bfloat16* __restrict__ Ah, const __nv_bfloat16* __restrict__ Al,
           const __nv_bfloat16* __restrict__ Whb, const __nv_bfloat16* __restrict__ Wlb,
           float* __restrict__ C,
           __nv_bfloat16* __restrict__ Ch0, __nv_bfloat16* __restrict__ Cl0,
           __nv_bfloat16* __restrict__ Ch1, __nv_bfloat16* __restrict__ Cl1,
           __nv_bfloat16* __restrict__ Ch2, __nv_bfloat16* __restrict__ Cl2) {
    const int t = threadIdx.x;
    const int lane = t & 31;
    const int wid = t >> 5;
    const int warp_m = wid >> 2;
    const int warp_n = wid & 3;
    const int bn = blockIdx.x << 7, bm = blockIdx.y << 7;
    const int z = blockIdx.z;

    const __nv_bfloat16* Wh = Whb + (size_t)z * DD * DD;
    const __nv_bfloat16* Wl = Wlb + (size_t)z * DD * DD;

    const uint32_t sb = smem_u32(dynsm);

    const __nv_bfloat16* gsrc[4] = {
        Ah + (size_t)bm * DD, Al + (size_t)bm * DD,
        Wh + (size_t)bn * DD, Wl + (size_t)bn * DD};

    const int r_ld = t >> 2;
    const int c_ld = (t & 3);

    const uint32_t aOff = (uint32_t)((warp_m * 64 + (lane & 15)) * PITCH +
                                     ((lane >> 4) & 1) * 16);
    const uint32_t bOff = (uint32_t)(warp_n * 32 * PITCH +
                                     ((lane & 7) + ((lane >> 4) << 3)) * PITCH +
                                     ((lane >> 3) & 1) * 16);

    float acc[4][4][4];
#pragma unroll
    for (int i = 0; i < 4; i++)
#pragma unroll
        for (int j = 0; j < 4; j++)
#pragma unroll
            for (int r = 0; r < 4; r++) acc[i][j][r] = 0.f;

#pragma unroll
    for (int tile = 0; tile < 4; tile++)
#pragma unroll
        for (int h = 0; h < 2; h++) {
            int row = r_ld + h * 64;
            uint32_t dst = sb + tile * TILE_B + row * PITCH + c_ld * 16;
            const void* src = gsrc[tile] + (size_t)row * DD + c_ld * 8;
            CPASYNC16(dst, src);
        }
    CPCOMMIT();

    for (int s = 0; s < NSTAGE_K; s++) {
        CPWAIT0();
        __syncthreads();

        if (s + 1 < NSTAGE_K) {
            const int k0 = (s + 1) * 32;
            const uint32_t stb = sb + ((s + 1) & 1) * STAGE_B;
#pragma unroll
            for (int tile = 0; tile < 4; tile++)
#pragma unroll
                for (int h = 0; h < 2; h++) {
                    int row = r_ld + h * 64;
                    uint32_t dst = stb + tile * TILE_B + row * PITCH + c_ld * 16;
                    const void* src = gsrc[tile] + (size_t)row * DD + k0 + c_ld * 8;
                    CPASYNC16(dst, src);
                }
            CPCOMMIT();
        }

        const uint32_t cb = sb + (s & 1) * STAGE_B;
        const uint32_t sAh = cb,              sAl = cb + TILE_B;
        const uint32_t sBh = cb + 2 * TILE_B, sBl = cb + 3 * TILE_B;

        // ---- stage-hoisted B fragments (both k-slices, both terms) ----
        uint32_t bh[2][8], bl[2][8];
#pragma unroll
        for (int ks = 0; ks < 2; ks++) {
            LDSM4(bh[ks][0], bh[ks][1], bh[ks][2], bh[ks][3], sBh + bOff + ks * 32);
            LDSM4(bh[ks][4], bh[ks][5], bh[ks][6], bh[ks][7], sBh + bOff + 16 * PITCH + ks * 32);
            LDSM4(bl[ks][0], bl[ks][1], bl[ks][2], bl[ks][3], sBl + bOff + ks * 32);
            LDSM4(bl[ks][4], bl[ks][5], bl[ks][6], bl[ks][7], sBl + bOff + 16 * PITCH + ks * 32);
        }

        // ---- A fragments: register double-buffer over 8 (mf,ks) iters ----
        uint32_t aF[2][2][4];   // [pingpong][term][frag]
        LDSM4(aF[0][0][0], aF[0][0][1], aF[0][0][2], aF[0][0][3], sAh + aOff);
        LDSM4(aF[0][1][0], aF[0][1][1], aF[0][1][2], aF[0][1][3], sAl + aOff);
#pragma unroll
        for (int it = 0; it < 8; it++) {
            const int mf = it >> 1, ks = it & 1;
            const int cur = it & 1, nxt = cur ^ 1;
            if (it + 1 < 8) {
                const int nmf = (it + 1) >> 1, nks = (it + 1) & 1;
                const uint32_t na = aOff + nmf * 16 * PITCH + nks * 32;
                LDSM4(aF[nxt][0][0], aF[nxt][0][1], aF[nxt][0][2], aF[nxt][0][3], sAh + na);
                LDSM4(aF[nxt][1][0], aF[nxt][1][1], aF[nxt][1][2], aF[nxt][1][3], sAl + na);
            }
            // product-major: hh, hl, lh (same-acc chains spaced by 4)
#pragma unroll
            for (int nf = 0; nf < 4; nf++)
                MMA16816(acc[mf][nf], aF[cur][0], &bh[ks][nf * 2]);
#pragma unroll
            for (int nf = 0; nf < 4; nf++)
                MMA16816(acc[mf][nf], aF[cur][0], &bl[ks][nf * 2]);
#pragma unroll
            for (int nf = 0; nf < 4; nf++)
                MMA16816(acc[mf][nf], aF[cur][1], &bh[ks][nf * 2]);
        }
    }

    if (Ch0 != nullptr) {
        __nv_bfloat16* Ch = (z == 0) ? Ch0 : (z == 1) ? Ch1 : Ch2;
        __nv_bfloat16* Cl = (z == 0) ? Cl0 : (z == 1) ? Cl1 : Cl2;
        const float scale = (z == 0) ? 0.125f : 1.0f;
#pragma unroll
        for (int mf = 0; mf < 4; mf++) {
            const int r0 = bm + warp_m * 64 + mf * 16 + (lane >> 2);
#pragma unroll
            for (int nf = 0; nf < 4; nf++) {
                const int cn = bn + warp_n * 32 + nf * 8 + (lane & 3) * 2;
#pragma unroll
                for (int hh = 0; hh < 2; hh++) {
                    float v0 = acc[mf][nf][hh * 2 + 0] * scale;
                    float v1 = acc[mf][nf][hh * 2 + 1] * scale;
                    uint32_t ph, pl;
                    PSPLIT(ph, pl, v0, v1);
                    size_t off = (size_t)(r0 + hh * 8) * DD + cn;
                    *(uint32_t*)&Ch[off] = ph;
                    *(uint32_t*)&Cl[off] = pl;
                }
            }
        }
    } else {
#pragma unroll
        for (int mf = 0; mf < 4; mf++) {
            const int r0 = bm + warp_m * 64 + mf * 16 + (lane >> 2);
#pragma unroll
            for (int nf = 0; nf < 4; nf++) {
                const int cn = bn + warp_n * 32 + nf * 8 + (lane & 3) * 2;
                *(float2*)&C[(size_t)r0 * DD + cn] =
                    make_float2(acc[mf][nf][0], acc[mf][nf][1]);
                *(float2*)&C[(size_t)(r0 + 8) * DD + cn] =
                    make_float2(acc[mf][nf][2], acc[mf][nf][3]);
            }
        }
    }
}

// ---------------------------------------------------------------------------
// Tensor-core sliding-window flash attention (unchanged from R4).
// ---------------------------------------------------------------------------
#define APITCH 144
#define ATILE (64 * APITCH)
#define ABUF  (4 * ATILE)

__global__ __launch_bounds__(256, 1)
void swa_mma(const __nv_bfloat16* __restrict__ Qh, const __nv_bfloat16* __restrict__ Ql,
             const __nv_bfloat16* __restrict__ Kh, const __nv_bfloat16* __restrict__ Kl,
             const __nv_bfloat16* __restrict__ Vh, const __nv_bfloat16* __restrict__ Vl,
             __nv_bfloat16* __restrict__ Oh, __nv_bfloat16* __restrict__ Ol) {
    const int jq = blockIdx.x, h = blockIdx.y, b = blockIdx.z;
    const int t = threadIdx.x, lane = t & 31, wid = t >> 5;
    const int tq = wid * 16;
    const uint32_t sb = smem_u32(dynsm);
    const int kv0 = 128 * jq - 256;

    uint32_t qA[2][4][4];
    {
        const int r0 = 128 * jq + tq + (lane >> 2);
        const size_t rowb = (size_t)(b * SS + r0) * DD + h * DH + 2 * (lane & 3);
        const __nv_bfloat16* Qs[2] = {Qh, Ql};
#pragma unroll
        for (int term = 0; term < 2; term++)
#pragma unroll
            for (int kf = 0; kf < 4; kf++) {
                qA[term][kf][0] = *(const uint32_t*)(Qs[term] + rowb + kf * 16);
                qA[term][kf][1] = *(const uint32_t*)(Qs[term] + rowb + 8 * DD + kf * 16);
                qA[term][kf][2] = *(const uint32_t*)(Qs[term] + rowb + kf * 16 + 8);
                qA[term][kf][3] = *(const uint32_t*)(Qs[term] + rowb + 8 * DD + kf * 16 + 8);
            }
    }

    const __nv_bfloat16* srcs[4] = {Kh, Kl, Vh, Vl};
    auto load_chunk = [&](int c, int buf) {
        const int kbase = kv0 + 64 * c;
#pragma unroll
        for (int it = 0; it < 8; it++) {
            int idx = t + it * 256;
            int tensor = idx >> 9;
            int row = (idx >> 3) & 63;
            int dch = idx & 7;
            int kp = kbase + row;
            int ok = (kp >= 0) ? 16 : 0;
            int kpc = kp >= 0 ? kp : 0;
            uint32_t dst = sb + buf * ABUF + tensor * ATILE + row * APITCH + dch * 16;
            const void* src = srcs[tensor] + (size_t)(b * SS + kpc) * DD + h * DH + dch * 8;
            CPASYNC16Z(dst, src, ok);
        }
    };

    float o[8][4];
#pragma unroll
    for (int nf = 0; nf < 8; nf++)
#pragma unroll
        for (int r = 0; r < 4; r++) o[nf][r] = 0.f;
    float m0 = -1e30f, m1 = -1e30f, lp0 = 0.f, lp1 = 0.f;

    const int cmin = (tq + 1) >> 6;
    const int cmax = (tq + 271) >> 6;

    load_chunk(0, 0);
    CPCOMMIT();

    for (int c = 0; c < 6; c++) {
        if (c < 5) {
            load_chunk(c + 1, (c + 1) & 1);
            CPCOMMIT();
            CPWAIT1();
        } else {
            CPWAIT0();
        }
        __syncthreads();

        const int kbase = kv0 + 64 * c;
        if (c >= cmin && c <= cmax && kbase + 63 >= 0) {
            const uint32_t kvb = sb + (c & 1) * ABUF;

            float s[8][4];
#pragma unroll
            for (int nf = 0; nf < 8; nf++)
#pragma unroll
                for (int r = 0; r < 4; r++) s[nf][r] = 0.f;

#pragma unroll
            for (int kf = 0; kf < 4; kf++) {
#pragma unroll
                for (int kg = 0; kg < 4; kg++) {
                    uint32_t addr = kvb +
                        (kg * 16 + (lane & 7) + ((lane >> 4) << 3)) * APITCH +
                        ((lane >> 3) & 1) * 16 + kf * 32;
                    uint32_t bh[4], bl[4];
                    LDSM4(bh[0], bh[1], bh[2], bh[3], addr);
                    LDSM4(bl[0], bl[1], bl[2], bl[3], addr + ATILE);
                    MMA16816(s[2 * kg],     qA[0][kf], &bh[0]);
                    MMA16816(s[2 * kg],     qA[0][kf], &bl[0]);
                    MMA16816(s[2 * kg],     qA[1][kf], &bh[0]);
                    MMA16816(s[2 * kg + 1], qA[0][kf], &bh[2]);
                    MMA16816(s[2 * kg + 1], qA[0][kf], &bl[2]);
                    MMA16816(s[2 * kg + 1], qA[1][kf], &bh[2]);
                }
            }

            {
                const int qg = 128 * jq + tq + (lane >> 2);
                const int d0 = qg - (kbase + 2 * (lane & 3));
#pragma unroll
                for (int nf = 0; nf < 8; nf++) {
                    int e = d0 - nf * 8;
                    s[nf][0] = ((unsigned)e <= 255u)       ? s[nf][0] : -1e30f;
                    s[nf][1] = ((unsigned)(e - 1) <= 255u) ? s[nf][1] : -1e30f;
                    s[nf][2] = ((unsigned)(e + 8) <= 255u) ? s[nf][2] : -1e30f;
                    s[nf][3] = ((unsigned)(e + 7) <= 255u) ? s[nf][3] : -1e30f;
                }
            }

            float mx0 = -1e30f, mx1 = -1e30f;
#pragma unroll
            for (int nf = 0; nf < 8; nf++) {
                mx0 = fmaxf(mx0, fmaxf(s[nf][0], s[nf][1]));
                mx1 = fmaxf(mx1, fmaxf(s[nf][2], s[nf][3]));
            }
            mx0 = fmaxf(mx0, __shfl_xor_sync(0xffffffffu, mx0, 1));
            mx0 = fmaxf(mx0, __shfl_xor_sync(0xffffffffu, mx0, 2));
            mx1 = fmaxf(mx1, __shfl_xor_sync(0xffffffffu, mx1, 1));
            mx1 = fmaxf(mx1, __shfl_xor_sync(0xffffffffu, mx1, 2));

            float mn0 = fmaxf(m0, mx0), mn1 = fmaxf(m1, mx1);
            float c0 = __expf(m0 - mn0), c1 = __expf(m1 - mn1);
            m0 = mn0; m1 = mn1;

            float ls0 = 0.f, ls1 = 0.f;
#pragma unroll
            for (int nf = 0; nf < 8; nf++) {
                s[nf][0] = __expf(s[nf][0] - mn0);
                s[nf][1] = __expf(s[nf][1] - mn0);
                s[nf][2] = __expf(s[nf][2] - mn1);
                s[nf][3] = __expf(s[nf][3] - mn1);
                ls0 += s[nf][0] + s[nf][1];
                ls1 += s[nf][2] + s[nf][3];
            }
            lp0 = lp0 * c0 + ls0;
            lp1 = lp1 * c1 + ls1;
#pragma unroll
            for (int nf = 0; nf < 8; nf++) {
                o[nf][0] *= c0; o[nf][1] *= c0;
                o[nf][2] *= c1; o[nf][3] *= c1;
            }

#pragma unroll
            for (int kf = 0; kf < 4; kf++) {
                uint32_t pha[4], pla[4];
                PSPLIT(pha[0], pla[0], s[2 * kf][0], s[2 * kf][1]);
                PSPLIT(pha[1], pla[1], s[2 * kf][2], s[2 * kf][3]);
                PSPLIT(pha[2], pla[2], s[2 * kf + 1][0], s[2 * kf + 1][1]);
                PSPLIT(pha[3], pla[3], s[2 * kf + 1][2], s[2 * kf + 1][3]);
#pragma unroll
                for (int dg = 0; dg < 4; dg++) {
                    uint32_t vaddr = kvb + 2 * ATILE +
                        (kf * 16 + (lane & 15)) * APITCH + dg * 32 +
                        ((lane >> 4) & 1) * 16;
                    uint32_t vh4[4], vl4[4];
                    LDSM4T(vh4[0], vh4[1], vh4[2], vh4[3], vaddr);
                    LDSM4T(vl4[0], vl4[1], vl4[2], vl4[3], vaddr + ATILE);
                    MMA16816(o[2 * dg],     pha, &vh4[0]);
                    MMA16816(o[2 * dg],     pha, &vl4[0]);
                    MMA16816(o[2 * dg],     pla, &vh4[0]);
                    MMA16816(o[2 * dg + 1], pha, &vh4[2]);
                    MMA16816(o[2 * dg + 1], pha, &vl4[2]);
                    MMA16816(o[2 * dg + 1], pla, &vh4[2]);
                }
            }
        }
        __syncthreads();
    }

    lp0 += __shfl_xor_sync(0xffffffffu, lp0, 1);
    lp0 += __shfl_xor_sync(0xffffffffu, lp0, 2);
    lp1 += __shfl_xor_sync(0xffffffffu, lp1, 1);
    lp1 += __shfl_xor_sync(0xffffffffu, lp1, 2);
    const float inv0 = 1.f / lp0, inv1 = 1.f / lp1;

    const int r0 = 128 * jq + tq + (lane >> 2);
    const size_t ob = (size_t)(b * SS + r0) * DD + h * DH + 2 * (lane & 3);
#pragma unroll
    for (int nf = 0; nf < 8; nf++) {
        float v0 = o[nf][0] * inv0, v1 = o[nf][1] * inv0;
        float v2 = o[nf][2] * inv1, v3 = o[nf][3] * inv1;
        uint32_t ph, pl;
        PSPLIT(ph, pl, v0, v1);
        *(uint32_t*)&Oh[ob + nf * 8] = ph;
        *(uint32_t*)&Ol[ob + nf * 8] = pl;
        PSPLIT(ph, pl, v2, v3);
        *(uint32_t*)&Oh[ob + 8 * DD + nf * 8] = ph;
        *(uint32_t*)&Ol[ob + 8 * DD + nf * 8] = pl;
    }
}

// ---------------------------------------------------------------------------
extern "C" void kernel_launch(void* const* d_in, const int* in_sizes, int n_in,
                              void* d_out, int out_size) {
    const float* x = (const float*)d_in[0];
    const float* w[4] = {(const float*)d_in[1], (const float*)d_in[2],
                         (const float*)d_in[3], (const float*)d_in[4]};
    float* out = (float*)d_out;

    __nv_bfloat16 *xh, *xl, *wh, *wl, *qh, *ql, *kh, *kl, *vh, *vl, *aoh, *aol;
    cudaGetSymbolAddress((void**)&xh, g_xh);
    cudaGetSymbolAddress((void**)&xl, g_xl);
    cudaGetSymbolAddress((void**)&wh, g_wh);
    cudaGetSymbolAddress((void**)&wl, g_wl);
    cudaGetSymbolAddress((void**)&qh, g_qh);
    cudaGetSymbolAddress((void**)&ql, g_ql);
    cudaGetSymbolAddress((void**)&kh, g_kh);
    cudaGetSymbolAddress((void**)&kl, g_kl);
    cudaGetSymbolAddress((void**)&vh, g_vh);
    cudaGetSymbolAddress((void**)&vl, g_vl);
    cudaGetSymbolAddress((void**)&aoh, g_aoh);
    cudaGetSymbolAddress((void**)&aol, g_aol);

    const int DYNSM_G = 2 * STAGE_B;
    const int DYNSM_A = 2 * ABUF;
    cudaFuncSetAttribute(tgemm, cudaFuncAttributeMaxDynamicSharedMemorySize, DYNSM_G);
    cudaFuncSetAttribute(swa_mma, cudaFuncAttributeMaxDynamicSharedMemorySize, DYNSM_A);

    split_bf16<<<(MM * DD) / 1024, 256>>>(x, xh, xl, MM * DD);
    for (int i = 0; i < 4; i++)
        split_bf16<<<(DD * DD) / 1024, 256>>>(w[i], wh + (size_t)i * DD * DD,
                                              wl + (size_t)i * DD * DD, DD * DD);

    // fused QKV: z=0 -> Q (scale 0.125), z=1 -> K, z=2 -> V
    dim3 gq(DD / 128, MM / 128, 3);
    tgemm<<<gq, 256, DYNSM_G>>>(xh, xl, wh, wl, nullptr,
                                qh, ql, kh, kl, vh, vl);

    dim3 ga(SS / 128, HH, BB);
    swa_mma<<<ga, 256, DYNSM_A>>>(qh, ql, kh, kl, vh, vl, aoh, aol);

    dim3 go(DD / 128, MM / 128, 1);
    tgemm<<<go, 256, DYNSM_G>>>(aoh, aol, wh + 3 * (size_t)DD * DD,
                                wl + 3 * (size_t)DD * DD, out,
                                nullptr, nullptr, nullptr, nullptr, nullptr, nullptr);
}

// round 6
// speedup vs baseline: 4.0256x; 1.2419x over previous
#include <cuda_runtime.h>
#include <cuda_bf16.h>
#include <math.h>
#include <stdint.h>

#define BB 2
#define SS 4096
#define DD 1024
#define HH 16
#define DH 64
#define WW 256
#define MM (BB * SS)

// ---------------- device scratch (allocation-free rule) ----------------
__device__ uint32_t g_xt[MM * DD];          // x in tf32, A-fragment-major
__device__ uint32_t g_wt[3 * DD * DD];      // wq,wk,wv in tf32, B-fragment-major
__device__ __nv_bfloat16 g_w3h[DD * DD];    // wo split bf16
__device__ __nv_bfloat16 g_w3l[DD * DD];
__device__ __nv_bfloat16 g_qh[MM * DD];
__device__ __nv_bfloat16 g_ql[MM * DD];
__device__ __nv_bfloat16 g_kh[MM * DD];
__device__ __nv_bfloat16 g_kl[MM * DD];
__device__ __nv_bfloat16 g_vh[MM * DD];
__device__ __nv_bfloat16 g_vl[MM * DD];
__device__ __nv_bfloat16 g_aoh[MM * DD];
__device__ __nv_bfloat16 g_aol[MM * DD];

// ---------------- family-portable PTX helpers ----------------
__device__ __forceinline__ uint32_t smem_u32(const void* p) {
    uint32_t a;
    asm("{ .reg .u64 t; cvta.to.shared.u64 t, %1; cvt.u32.u64 %0, t; }"
        : "=r"(a) : "l"(p));
    return a;
}
__device__ __forceinline__ uint32_t f2tf32(float f) {
    uint32_t u;
    asm("cvt.rna.tf32.f32 %0, %1;" : "=r"(u) : "f"(f));
    return u;
}

#define LDSM4(r0, r1, r2, r3, addr)                                              \
    asm volatile("ldmatrix.sync.aligned.m8n8.x4.shared.b16 {%0,%1,%2,%3}, [%4];"  \
                 : "=r"(r0), "=r"(r1), "=r"(r2), "=r"(r3) : "r"(addr))
#define LDSM4T(r0, r1, r2, r3, addr)                                             \
    asm volatile("ldmatrix.sync.aligned.m8n8.x4.trans.shared.b16 {%0,%1,%2,%3}, [%4];" \
                 : "=r"(r0), "=r"(r1), "=r"(r2), "=r"(r3) : "r"(addr))
#define LDS128U(r, addr)                                                         \
    asm volatile("ld.shared.v4.b32 {%0,%1,%2,%3}, [%4];"                          \
                 : "=r"((r)[0]), "=r"((r)[1]), "=r"((r)[2]), "=r"((r)[3])         \
                 : "r"(addr))
#define LDS64U(r, addr)                                                          \
    asm volatile("ld.shared.v2.b32 {%0,%1}, [%2];"                                \
                 : "=r"((r)[0]), "=r"((r)[1]) : "r"(addr))

#define MMA16816(d, a, b)                                                        \
    asm volatile(                                                                \
        "mma.sync.aligned.m16n8k16.row.col.f32.bf16.bf16.f32 "                   \
        "{%0,%1,%2,%3},{%4,%5,%6,%7},{%8,%9},{%0,%1,%2,%3};"                     \
        : "+f"((d)[0]), "+f"((d)[1]), "+f"((d)[2]), "+f"((d)[3])                 \
        : "r"((a)[0]), "r"((a)[1]), "r"((a)[2]), "r"((a)[3]),                    \
          "r"((b)[0]), "r"((b)[1]))
#define MMATF32(d, a, b)                                                         \
    asm volatile(                                                                \
        "mma.sync.aligned.m16n8k8.row.col.f32.tf32.tf32.f32 "                    \
        "{%0,%1,%2,%3},{%4,%5,%6,%7},{%8,%9},{%0,%1,%2,%3};"                     \
        : "+f"((d)[0]), "+f"((d)[1]), "+f"((d)[2]), "+f"((d)[3])                 \
        : "r"((a)[0]), "r"((a)[1]), "r"((a)[2]), "r"((a)[3]),                    \
          "r"((b)[0]), "r"((b)[1]))

#define CPASYNC16(dst, src)                                                      \
    asm volatile("cp.async.cg.shared.global [%0], [%1], 16;" :: "r"(dst), "l"(src))
#define CPASYNC16Z(dst, src, sz)                                                 \
    asm volatile("cp.async.cg.shared.global [%0], [%1], 16, %2;"                  \
                 :: "r"(dst), "l"(src), "r"(sz))
#define CPCOMMIT() asm volatile("cp.async.commit_group;" ::: "memory")
#define CPWAIT0()  asm volatile("cp.async.wait_group 0;" ::: "memory")
#define CPWAIT1()  asm volatile("cp.async.wait_group 1;" ::: "memory")

#define PSPLIT(ph, pl, va, vb)                                                   \
    {                                                                            \
        __nv_bfloat162 _h = __float22bfloat162_rn(make_float2((va), (vb)));      \
        float _ra = (va) - __bfloat162float(__low2bfloat16(_h));                 \
        float _rb = (vb) - __bfloat162float(__high2bfloat16(_h));                \
        __nv_bfloat162 _l = __float22bfloat162_rn(make_float2(_ra, _rb));        \
        (ph) = *(uint32_t*)&_h;                                                  \
        (pl) = *(uint32_t*)&_l;                                                  \
    }

extern __shared__ char dynsm[];

// ---------------------------------------------------------------------------
// Converters
// ---------------------------------------------------------------------------
__global__ __launch_bounds__(256) void split_bf16(const float* __restrict__ s,
                                                  __nv_bfloat16* __restrict__ hi,
                                                  __nv_bfloat16* __restrict__ lo,
                                                  int n) {
    int i = (blockIdx.x * 256 + threadIdx.x) * 4;
    if (i >= n) return;
    float4 v = *(const float4*)(s + i);
    float f[4] = {v.x, v.y, v.z, v.w};
    __nv_bfloat16 h[4], l[4];
#pragma unroll
    for (int j = 0; j < 4; j++) {
        h[j] = __float2bfloat16(f[j]);
        l[j] = __float2bfloat16(f[j] - __bfloat162float(h[j]));
    }
    *(__nv_bfloat162*)(hi + i)     = __halves2bfloat162(h[0], h[1]);
    *(__nv_bfloat162*)(hi + i + 2) = __halves2bfloat162(h[2], h[3]);
    *(__nv_bfloat162*)(lo + i)     = __halves2bfloat162(l[0], l[1]);
    *(__nv_bfloat162*)(lo + i + 2) = __halves2bfloat162(l[2], l[3]);
}

// x[r][c] -> tf32 A-fragment-major:
// block(rb,kb) of 16x8; lane = (ri&7)*4 + (ci&3); j = (ri>>3) + 2*(ci>>2)
// out[(rb*128 + kb)*128 + lane*4 + j]
__global__ __launch_bounds__(256) void conv_a_tf32(const float* __restrict__ x,
                                                   uint32_t* __restrict__ out) {
    int i = (blockIdx.x * 256 + threadIdx.x) * 4;
    float4 v = *(const float4*)(x + i);
    float f[4] = {v.x, v.y, v.z, v.w};
    int r = i >> 10, c = i & 1023;             // DD = 1024
    int rb = r >> 4, ri = r & 15, kb = c >> 3;
    int jj = (ri >> 3) + 2 * ((c & 7) >> 2);   // same for all 4 (c % 4 == 0)
    uint32_t* o = out + ((size_t)(rb * 128 + kb) << 7) + jj;
    int lane0 = (ri & 7) * 4;
#pragma unroll
    for (int m = 0; m < 4; m++) o[(lane0 + m) << 2] = f2tf32(f[m]);
}

// W[n][k] -> tf32 B-fragment-major (B[k][n] = W[n][k]):
// block(nb,kb) of k8 x n8; lane = (ni)*4 + (ki&3); j = ki>>2
// out[(nb*128 + kb)*64 + lane*2 + j]
__global__ __launch_bounds__(256) void conv_b_tf32(const float* __restrict__ w0,
                                                   const float* __restrict__ w1,
                                                   const float* __restrict__ w2,
                                                   uint32_t* __restrict__ out) {
    const int z = blockIdx.y;
    const float* w = (z == 0) ? w0 : (z == 1) ? w1 : w2;
    uint32_t* ob = out + (size_t)z * DD * DD;
    int i = (blockIdx.x * 256 + threadIdx.x) * 4;
    float4 v = *(const float4*)(w + i);
    float f[4] = {v.x, v.y, v.z, v.w};
    int n = i >> 10, k = i & 1023;
    int nb = n >> 3, ni = n & 7, kb = k >> 3;
    int j = (k & 7) >> 2;                      // same for all 4
    uint32_t* o = ob + ((size_t)(nb * 128 + kb) << 6) + j;
    int lane0 = ni * 4;
#pragma unroll
    for (int m = 0; m < 4; m++) o[(lane0 + m) << 1] = f2tf32(f[m]);
}

// ---------------------------------------------------------------------------
// tf32 single-pass QKV GEMM. 128x128 tile, BK=32, 3-stage cp.async,
// fragment-major smem (no ldmatrix, conflict-free LDS.128/LDS.64).
// Epilogue: split-bf16 (Q scaled by 0.125).
// ---------------------------------------------------------------------------
#define T32_STAGE 32768        // A 16KB + B 16KB

__global__ __launch_bounds__(256, 2)
void tgemm32(const uint32_t* __restrict__ At, const uint32_t* __restrict__ Wt,
             __nv_bfloat16* __restrict__ Ch0, __nv_bfloat16* __restrict__ Cl0,
             __nv_bfloat16* __restrict__ Ch1, __nv_bfloat16* __restrict__ Cl1,
             __nv_bfloat16* __restrict__ Ch2, __nv_bfloat16* __restrict__ Cl2) {
    const int t = threadIdx.x;
    const int lane = t & 31;
    const int wid = t >> 5;
    const int warp_m = wid >> 2;   // 0..1
    const int warp_n = wid & 3;    // 0..3
    const int z = blockIdx.z;

    const uint32_t sb = smem_u32(dynsm);

    const uint32_t* A0 = At + ((size_t)(blockIdx.y * 8) << 14);          // rb0*128*128
    const uint32_t* B0 = Wt + (size_t)z * DD * DD + ((size_t)(blockIdx.x * 16) << 13); // nb0*128*64

    float acc[4][4][4];
#pragma unroll
    for (int i = 0; i < 4; i++)
#pragma unroll
        for (int j = 0; j < 4; j++)
#pragma unroll
            for (int r = 0; r < 4; r++) acc[i][j][r] = 0.f;

    auto load_stage = [&](int s, int buf) {
        const int kb0 = s * 4;
        const uint32_t base = sb + buf * T32_STAGE;
#pragma unroll
        for (int it = 0; it < 4; it++) {
            int c = t + it * 256;  // 0..1023
            // A chunk
            const uint32_t* ga = A0 +
                ((size_t)(((c >> 7) << 7) + kb0 + ((c >> 5) & 3)) << 7) + ((c & 31) << 2);
            CPASYNC16(base + c * 16, ga);
            // B chunk
            const uint32_t* gb = B0 +
                ((size_t)(((c >> 6) << 7) + kb0 + ((c >> 4) & 3)) << 6) + ((c & 15) << 2);
            CPASYNC16(base + 16384 + c * 16, gb);
        }
    };

    load_stage(0, 0); CPCOMMIT();
    load_stage(1, 1); CPCOMMIT();

    for (int s = 0; s < 32; s++) {
        CPWAIT1();
        __syncthreads();
        if (s + 2 < 32) load_stage(s + 2, (s + 2) % 3);
        CPCOMMIT();

        const uint32_t sA = sb + (s % 3) * T32_STAGE;
        const uint32_t sB = sA + 16384;

        // hoist all B fragments: 4 ks x 4 nf x LDS.64 (conflict-free)
        uint32_t bf[4][4][2];
#pragma unroll
        for (int ks = 0; ks < 4; ks++)
#pragma unroll
            for (int nf = 0; nf < 4; nf++)
                LDS64U(bf[ks][nf],
                       sB + ((((warp_n * 4 + nf) << 2) + ks) << 8) + lane * 8);

        // A: register double-buffer over 16 (mf,ks) iterations
        uint32_t ap[2][4];
        LDS128U(ap[0], sA + (((warp_m * 4) << 2) << 9) + lane * 16);
#pragma unroll
        for (int it = 0; it < 16; it++) {
            const int mf = it >> 2, ks = it & 3;
            if (it < 15) {
                const int nmf = (it + 1) >> 2, nks = (it + 1) & 3;
                LDS128U(ap[(it + 1) & 1],
                        sA + ((((warp_m * 4 + nmf) << 2) + nks) << 9) + lane * 16);
            }
#pragma unroll
            for (int nf = 0; nf < 4; nf++)
                MMATF32(acc[mf][nf], ap[it & 1], bf[ks][nf]);
        }
    }

    __nv_bfloat16* Ch = (z == 0) ? Ch0 : (z == 1) ? Ch1 : Ch2;
    __nv_bfloat16* Cl = (z == 0) ? Cl0 : (z == 1) ? Cl1 : Cl2;
    const float scale = (z == 0) ? 0.125f : 1.0f;
    const int bm = blockIdx.y << 7, bn = blockIdx.x << 7;
#pragma unroll
    for (int mf = 0; mf < 4; mf++) {
        const int r0 = bm + warp_m * 64 + mf * 16 + (lane >> 2);
#pragma unroll
        for (int nf = 0; nf < 4; nf++) {
            const int cn = bn + warp_n * 32 + nf * 8 + (lane & 3) * 2;
#pragma unroll
            for (int hh = 0; hh < 2; hh++) {
                float v0 = acc[mf][nf][hh * 2 + 0] * scale;
                float v1 = acc[mf][nf][hh * 2 + 1] * scale;
                uint32_t ph, pl;
                PSPLIT(ph, pl, v0, v1);
                size_t off = (size_t)(r0 + hh * 8) * DD + cn;
                *(uint32_t*)&Ch[off] = ph;
                *(uint32_t*)&Cl[off] = pl;
            }
        }
    }
}

// ---------------------------------------------------------------------------
// bf16 3-term GEMM (O projection only) — unchanged R5 mainloop, fp32 out.
// ---------------------------------------------------------------------------
#define PITCH 80
#define TILE_B (128 * PITCH)
#define STAGE_B (4 * TILE_B)

__global__ __launch_bounds__(256, 2)
void tgemm(const __nv_bfloat16* __restrict__ Ah, const __nv_bfloat16* __restrict__ Al,
           const __nv_bfloat16* __restrict__ Wh, const __nv_bfloat16* __restrict__ Wl,
           float* __restrict__ C) {
    const int t = threadIdx.x;
    const int lane = t & 31;
    const int wid = t >> 5;
    const int warp_m = wid >> 2;
    const int warp_n = wid & 3;
    const int bn = blockIdx.x << 7, bm = blockIdx.y << 7;

    const uint32_t sb = smem_u32(dynsm);

    const __nv_bfloat16* gsrc[4] = {
        Ah + (size_t)bm * DD, Al + (size_t)bm * DD,
        Wh + (size_t)bn * DD, Wl + (size_t)bn * DD};

    const int r_ld = t >> 2;
    const int c_ld = (t & 3);

    const uint32_t aOff = (uint32_t)((warp_m * 64 + (lane & 15)) * PITCH +
                                     ((lane >> 4) & 1) * 16);
    const uint32_t bOff = (uint32_t)(warp_n * 32 * PITCH +
                                     ((lane & 7) + ((lane >> 4) << 3)) * PITCH +
                                     ((lane >> 3) & 1) * 16);

    float acc[4][4][4];
#pragma unroll
    for (int i = 0; i < 4; i++)
#pragma unroll
        for (int j = 0; j < 4; j++)
#pragma unroll
            for (int r = 0; r < 4; r++) acc[i][j][r] = 0.f;

#pragma unroll
    for (int tile = 0; tile < 4; tile++)
#pragma unroll
        for (int h = 0; h < 2; h++) {
            int row = r_ld + h * 64;
            uint32_t dst = sb + tile * TILE_B + row * PITCH + c_ld * 16;
            const void* src = gsrc[tile] + (size_t)row * DD + c_ld * 8;
            CPASYNC16(dst, src);
        }
    CPCOMMIT();

    for (int s = 0; s < 32; s++) {
        CPWAIT0();
        __syncthreads();

        if (s + 1 < 32) {
            const int k0 = (s + 1) * 32;
            const uint32_t stb = sb + ((s + 1) & 1) * STAGE_B;
#pragma unroll
            for (int tile = 0; tile < 4; tile++)
#pragma unroll
                for (int h = 0; h < 2; h++) {
                    int row = r_ld + h * 64;
                    uint32_t dst = stb + tile * TILE_B + row * PITCH + c_ld * 16;
                    const void* src = gsrc[tile] + (size_t)row * DD + k0 + c_ld * 8;
                    CPASYNC16(dst, src);
                }
            CPCOMMIT();
        }

        const uint32_t cb = sb + (s & 1) * STAGE_B;
        const uint32_t sAh = cb,              sAl = cb + TILE_B;
        const uint32_t sBh = cb + 2 * TILE_B, sBl = cb + 3 * TILE_B;

        uint32_t bh[2][8], bl[2][8];
#pragma unroll
        for (int ks = 0; ks < 2; ks++) {
            LDSM4(bh[ks][0], bh[ks][1], bh[ks][2], bh[ks][3], sBh + bOff + ks * 32);
            LDSM4(bh[ks][4], bh[ks][5], bh[ks][6], bh[ks][7], sBh + bOff + 16 * PITCH + ks * 32);
            LDSM4(bl[ks][0], bl[ks][1], bl[ks][2], bl[ks][3], sBl + bOff + ks * 32);
            LDSM4(bl[ks][4], bl[ks][5], bl[ks][6], bl[ks][7], sBl + bOff + 16 * PITCH + ks * 32);
        }

        uint32_t aF[2][2][4];
        LDSM4(aF[0][0][0], aF[0][0][1], aF[0][0][2], aF[0][0][3], sAh + aOff);
        LDSM4(aF[0][1][0], aF[0][1][1], aF[0][1][2], aF[0][1][3], sAl + aOff);
#pragma unroll
        for (int it = 0; it < 8; it++) {
            const int mf = it >> 1, ks = it & 1;
            const int cur = it & 1, nxt = cur ^ 1;
            if (it + 1 < 8) {
                const int nmf = (it + 1) >> 1, nks = (it + 1) & 1;
                const uint32_t na = aOff + nmf * 16 * PITCH + nks * 32;
                LDSM4(aF[nxt][0][0], aF[nxt][0][1], aF[nxt][0][2], aF[nxt][0][3], sAh + na);
                LDSM4(aF[nxt][1][0], aF[nxt][1][1], aF[nxt][1][2], aF[nxt][1][3], sAl + na);
            }
#pragma unroll
            for (int nf = 0; nf < 4; nf++)
                MMA16816(acc[mf][nf], aF[cur][0], &bh[ks][nf * 2]);
#pragma unroll
            for (int nf = 0; nf < 4; nf++)
                MMA16816(acc[mf][nf], aF[cur][0], &bl[ks][nf * 2]);
#pragma unroll
            for (int nf = 0; nf < 4; nf++)
                MMA16816(acc[mf][nf], aF[cur][1], &bh[ks][nf * 2]);
        }
    }

#pragma unroll
    for (int mf = 0; mf < 4; mf++) {
        const int r0 = bm + warp_m * 64 + mf * 16 + (lane >> 2);
#pragma unroll
        for (int nf = 0; nf < 4; nf++) {
            const int cn = bn + warp_n * 32 + nf * 8 + (lane & 3) * 2;
            *(float2*)&C[(size_t)r0 * DD + cn] =
                make_float2(acc[mf][nf][0], acc[mf][nf][1]);
            *(float2*)&C[(size_t)(r0 + 8) * DD + cn] =
                make_float2(acc[mf][nf][2], acc[mf][nf][3]);
        }
    }
}

// ---------------------------------------------------------------------------
// Tensor-core sliding-window flash attention (unchanged).
// ---------------------------------------------------------------------------
#define APITCH 144
#define ATILE (64 * APITCH)
#define ABUF  (4 * ATILE)

__global__ __launch_bounds__(256, 1)
void swa_mma(const __nv_bfloat16* __restrict__ Qh, const __nv_bfloat16* __restrict__ Ql,
             const __nv_bfloat16* __restrict__ Kh, const __nv_bfloat16* __restrict__ Kl,
             const __nv_bfloat16* __restrict__ Vh, const __nv_bfloat16* __restrict__ Vl,
             __nv_bfloat16* __restrict__ Oh, __nv_bfloat16* __restrict__ Ol) {
    const int jq = blockIdx.x, h = blockIdx.y, b = blockIdx.z;
    const int t = threadIdx.x, lane = t & 31, wid = t >> 5;
    const int tq = wid * 16;
    const uint32_t sb = smem_u32(dynsm);
    const int kv0 = 128 * jq - 256;

    uint32_t qA[2][4][4];
    {
        const int r0 = 128 * jq + tq + (lane >> 2);
        const size_t rowb = (size_t)(b * SS + r0) * DD + h * DH + 2 * (lane & 3);
        const __nv_bfloat16* Qs[2] = {Qh, Ql};
#pragma unroll
        for (int term = 0; term < 2; term++)
#pragma unroll
            for (int kf = 0; kf < 4; kf++) {
                qA[term][kf][0] = *(const uint32_t*)(Qs[term] + rowb + kf * 16);
                qA[term][kf][1] = *(const uint32_t*)(Qs[term] + rowb + 8 * DD + kf * 16);
                qA[term][kf][2] = *(const uint32_t*)(Qs[term] + rowb + kf * 16 + 8);
                qA[term][kf][3] = *(const uint32_t*)(Qs[term] + rowb + 8 * DD + kf * 16 + 8);
            }
    }

    const __nv_bfloat16* srcs[4] = {Kh, Kl, Vh, Vl};
    auto load_chunk = [&](int c, int buf) {
        const int kbase = kv0 + 64 * c;
#pragma unroll
        for (int it = 0; it < 8; it++) {
            int idx = t + it * 256;
            int tensor = idx >> 9;
            int row = (idx >> 3) & 63;
            int dch = idx & 7;
            int kp = kbase + row;
            int ok = (kp >= 0) ? 16 : 0;
            int kpc = kp >= 0 ? kp : 0;
            uint32_t dst = sb + buf * ABUF + tensor * ATILE + row * APITCH + dch * 16;
            const void* src = srcs[tensor] + (size_t)(b * SS + kpc) * DD + h * DH + dch * 8;
            CPASYNC16Z(dst, src, ok);
        }
    };

    float o[8][4];
#pragma unroll
    for (int nf = 0; nf < 8; nf++)
#pragma unroll
        for (int r = 0; r < 4; r++) o[nf][r] = 0.f;
    float m0 = -1e30f, m1 = -1e30f, lp0 = 0.f, lp1 = 0.f;

    const int cmin = (tq + 1) >> 6;
    const int cmax = (tq + 271) >> 6;

    load_chunk(0, 0);
    CPCOMMIT();

    for (int c = 0; c < 6; c++) {
        if (c < 5) {
            load_chunk(c + 1, (c + 1) & 1);
            CPCOMMIT();
            CPWAIT1();
        } else {
            CPWAIT0();
        }
        __syncthreads();

        const int kbase = kv0 + 64 * c;
        if (c >= cmin && c <= cmax && kbase + 63 >= 0) {
            const uint32_t kvb = sb + (c & 1) * ABUF;

            float s[8][4];
#pragma unroll
            for (int nf = 0; nf < 8; nf++)
#pragma unroll
                for (int r = 0; r < 4; r++) s[nf][r] = 0.f;

#pragma unroll
            for (int kf = 0; kf < 4; kf++) {
#pragma unroll
                for (int kg = 0; kg < 4; kg++) {
                    uint32_t addr = kvb +
                        (kg * 16 + (lane & 7) + ((lane >> 4) << 3)) * APITCH +
                        ((lane >> 3) & 1) * 16 + kf * 32;
                    uint32_t bh[4], bl[4];
                    LDSM4(bh[0], bh[1], bh[2], bh[3], addr);
                    LDSM4(bl[0], bl[1], bl[2], bl[3], addr + ATILE);
                    MMA16816(s[2 * kg],     qA[0][kf], &bh[0]);
                    MMA16816(s[2 * kg],     qA[0][kf], &bl[0]);
                    MMA16816(s[2 * kg],     qA[1][kf], &bh[0]);
                    MMA16816(s[2 * kg + 1], qA[0][kf], &bh[2]);
                    MMA16816(s[2 * kg + 1], qA[0][kf], &bl[2]);
                    MMA16816(s[2 * kg + 1], qA[1][kf], &bh[2]);
                }
            }

            {
                const int qg = 128 * jq + tq + (lane >> 2);
                const int d0 = qg - (kbase + 2 * (lane & 3));
#pragma unroll
                for (int nf = 0; nf < 8; nf++) {
                    int e = d0 - nf * 8;
                    s[nf][0] = ((unsigned)e <= 255u)       ? s[nf][0] : -1e30f;
                    s[nf][1] = ((unsigned)(e - 1) <= 255u) ? s[nf][1] : -1e30f;
                    s[nf][2] = ((unsigned)(e + 8) <= 255u) ? s[nf][2] : -1e30f;
                    s[nf][3] = ((unsigned)(e + 7) <= 255u) ? s[nf][3] : -1e30f;
                }
            }

            float mx0 = -1e30f, mx1 = -1e30f;
#pragma unroll
            for (int nf = 0; nf < 8; nf++) {
                mx0 = fmaxf(mx0, fmaxf(s[nf][0], s[nf][1]));
                mx1 = fmaxf(mx1, fmaxf(s[nf][2], s[nf][3]));
            }
            mx0 = fmaxf(mx0, __shfl_xor_sync(0xffffffffu, mx0, 1));
            mx0 = fmaxf(mx0, __shfl_xor_sync(0xffffffffu, mx0, 2));
            mx1 = fmaxf(mx1, __shfl_xor_sync(0xffffffffu, mx1, 1));
            mx1 = fmaxf(mx1, __shfl_xor_sync(0xffffffffu, mx1, 2));

            float mn0 = fmaxf(m0, mx0), mn1 = fmaxf(m1, mx1);
            float c0 = __expf(m0 - mn0), c1 = __expf(m1 - mn1);
            m0 = mn0; m1 = mn1;

            float ls0 = 0.f, ls1 = 0.f;
#pragma unroll
            for (int nf = 0; nf < 8; nf++) {
                s[nf][0] = __expf(s[nf][0] - mn0);
                s[nf][1] = __expf(s[nf][1] - mn0);
                s[nf][2] = __expf(s[nf][2] - mn1);
                s[nf][3] = __expf(s[nf][3] - mn1);
                ls0 += s[nf][0] + s[nf][1];
                ls1 += s[nf][2] + s[nf][3];
            }
            lp0 = lp0 * c0 + ls0;
            lp1 = lp1 * c1 + ls1;
#pragma unroll
            for (int nf = 0; nf < 8; nf++) {
                o[nf][0] *= c0; o[nf][1] *= c0;
                o[nf][2] *= c1; o[nf][3] *= c1;
            }

#pragma unroll
            for (int kf = 0; kf < 4; kf++) {
                uint32_t pha[4], pla[4];
                PSPLIT(pha[0], pla[0], s[2 * kf][0], s[2 * kf][1]);
                PSPLIT(pha[1], pla[1], s[2 * kf][2], s[2 * kf][3]);
                PSPLIT(pha[2], pla[2], s[2 * kf + 1][0], s[2 * kf + 1][1]);
                PSPLIT(pha[3], pla[3], s[2 * kf + 1][2], s[2 * kf + 1][3]);
#pragma unroll
                for (int dg = 0; dg < 4; dg++) {
                    uint32_t vaddr = kvb + 2 * ATILE +
                        (kf * 16 + (lane & 15)) * APITCH + dg * 32 +
                        ((lane >> 4) & 1) * 16;
                    uint32_t vh4[4], vl4[4];
                    LDSM4T(vh4[0], vh4[1], vh4[2], vh4[3], vaddr);
                    LDSM4T(vl4[0], vl4[1], vl4[2], vl4[3], vaddr + ATILE);
                    MMA16816(o[2 * dg],     pha, &vh4[0]);
                    MMA16816(o[2 * dg],     pha, &vl4[0]);
                    MMA16816(o[2 * dg],     pla, &vh4[0]);
                    MMA16816(o[2 * dg + 1], pha, &vh4[2]);
                    MMA16816(o[2 * dg + 1], pha, &vl4[2]);
                    MMA16816(o[2 * dg + 1], pla, &vh4[2]);
                }
            }
        }
        __syncthreads();
    }

    lp0 += __shfl_xor_sync(0xffffffffu, lp0, 1);
    lp0 += __shfl_xor_sync(0xffffffffu, lp0, 2);
    lp1 += __shfl_xor_sync(0xffffffffu, lp1, 1);
    lp1 += __shfl_xor_sync(0xffffffffu, lp1, 2);
    const float inv0 = 1.f / lp0, inv1 = 1.f / lp1;

    const int r0 = 128 * jq + tq + (lane >> 2);
    const size_t ob = (size_t)(b * SS + r0) * DD + h * DH + 2 * (lane & 3);
#pragma unroll
    for (int nf = 0; nf < 8; nf++) {
        float v0 = o[nf][0] * inv0, v1 = o[nf][1] * inv0;
        float v2 = o[nf][2] * inv1, v3 = o[nf][3] * inv1;
        uint32_t ph, pl;
        PSPLIT(ph, pl, v0, v1);
        *(uint32_t*)&Oh[ob + nf * 8] = ph;
        *(uint32_t*)&Ol[ob + nf * 8] = pl;
        PSPLIT(ph, pl, v2, v3);
        *(uint32_t*)&Oh[ob + 8 * DD + nf * 8] = ph;
        *(uint32_t*)&Ol[ob + 8 * DD + nf * 8] = pl;
    }
}

// ---------------------------------------------------------------------------
extern "C" void kernel_launch(void* const* d_in, const int* in_sizes, int n_in,
                              void* d_out, int out_size) {
    const float* x = (const float*)d_in[0];
    const float* w[4] = {(const float*)d_in[1], (const float*)d_in[2],
                         (const float*)d_in[3], (const float*)d_in[4]};
    float* out = (float*)d_out;

    uint32_t *xt, *wt;
    __nv_bfloat16 *w3h, *w3l, *qh, *ql, *kh, *kl, *vh, *vl, *aoh, *aol;
    cudaGetSymbolAddress((void**)&xt,  g_xt);
    cudaGetSymbolAddress((void**)&wt,  g_wt);
    cudaGetSymbolAddress((void**)&w3h, g_w3h);
    cudaGetSymbolAddress((void**)&w3l, g_w3l);
    cudaGetSymbolAddress((void**)&qh,  g_qh);
    cudaGetSymbolAddress((void**)&ql,  g_ql);
    cudaGetSymbolAddress((void**)&kh,  g_kh);
    cudaGetSymbolAddress((void**)&kl,  g_kl);
    cudaGetSymbolAddress((void**)&vh,  g_vh);
    cudaGetSymbolAddress((void**)&vl,  g_vl);
    cudaGetSymbolAddress((void**)&aoh, g_aoh);
    cudaGetSymbolAddress((void**)&aol, g_aol);

    const int DYNSM_T = 3 * T32_STAGE;    // 98304
    const int DYNSM_G = 2 * STAGE_B;      // 81920
    const int DYNSM_A = 2 * ABUF;         // 73728
    cudaFuncSetAttribute(tgemm32, cudaFuncAttributeMaxDynamicSharedMemorySize, DYNSM_T);
    cudaFuncSetAttribute(tgemm,   cudaFuncAttributeMaxDynamicSharedMemorySize, DYNSM_G);
    cudaFuncSetAttribute(swa_mma, cudaFuncAttributeMaxDynamicSharedMemorySize, DYNSM_A);

    conv_a_tf32<<<(MM * DD) / 1024, 256>>>(x, xt);
    conv_b_tf32<<<dim3((DD * DD) / 1024, 3), 256>>>(w[0], w[1], w[2], wt);
    split_bf16<<<(DD * DD) / 1024, 256>>>(w[3], w3h, w3l, DD * DD);

    dim3 gq(DD / 128, MM / 128, 3);   // (8, 64, 3)
    tgemm32<<<gq, 256, DYNSM_T>>>(xt, wt, qh, ql, kh, kl, vh, vl);

    dim3 ga(SS / 128, HH, BB);        // (32, 16, 2)
    swa_mma<<<ga, 256, DYNSM_A>>>(qh, ql, kh, kl, vh, vl, aoh, aol);

    dim3 go(DD / 128, MM / 128);      // (8, 64)
    tgemm<<<go, 256, DYNSM_G>>>(aoh, aol, w3h, w3l, out);
}

// round 7
// speedup vs baseline: 4.3628x; 1.0838x over previous
#include <cuda_runtime.h>
#include <cuda_bf16.h>
#include <math.h>
#include <stdint.h>

#define BB 2
#define SS 4096
#define DD 1024
#define HH 16
#define DH 64
#define WW 256
#define MM (BB * SS)

// ---------------- device scratch (allocation-free rule) ----------------
__device__ uint32_t g_xt[MM * DD];          // x (then ao) in tf32, A-fragment-major
__device__ uint32_t g_wt[4 * DD * DD];      // wq,wk,wv,wo in tf32, B-fragment-major
__device__ float g_ao[MM * DD];             // attention output, fp32
__device__ __nv_bfloat16 g_qh[MM * DD];
__device__ __nv_bfloat16 g_ql[MM * DD];
__device__ __nv_bfloat16 g_kh[MM * DD];
__device__ __nv_bfloat16 g_kl[MM * DD];
__device__ __nv_bfloat16 g_vh[MM * DD];
__device__ __nv_bfloat16 g_vl[MM * DD];

// ---------------- family-portable PTX helpers ----------------
__device__ __forceinline__ uint32_t smem_u32(const void* p) {
    uint32_t a;
    asm("{ .reg .u64 t; cvta.to.shared.u64 t, %1; cvt.u32.u64 %0, t; }"
        : "=r"(a) : "l"(p));
    return a;
}
__device__ __forceinline__ uint32_t f2tf32(float f) {
    uint32_t u;
    asm("cvt.rna.tf32.f32 %0, %1;" : "=r"(u) : "f"(f));
    return u;
}

#define LDSM4(r0, r1, r2, r3, addr)                                              \
    asm volatile("ldmatrix.sync.aligned.m8n8.x4.shared.b16 {%0,%1,%2,%3}, [%4];"  \
                 : "=r"(r0), "=r"(r1), "=r"(r2), "=r"(r3) : "r"(addr))
#define LDSM4T(r0, r1, r2, r3, addr)                                             \
    asm volatile("ldmatrix.sync.aligned.m8n8.x4.trans.shared.b16 {%0,%1,%2,%3}, [%4];" \
                 : "=r"(r0), "=r"(r1), "=r"(r2), "=r"(r3) : "r"(addr))
#define LDS128U(r, addr)                                                         \
    asm volatile("ld.shared.v4.b32 {%0,%1,%2,%3}, [%4];"                          \
                 : "=r"((r)[0]), "=r"((r)[1]), "=r"((r)[2]), "=r"((r)[3])         \
                 : "r"(addr))
#define LDS64U(r, addr)                                                          \
    asm volatile("ld.shared.v2.b32 {%0,%1}, [%2];"                                \
                 : "=r"((r)[0]), "=r"((r)[1]) : "r"(addr))

#define MMA16816(d, a, b)                                                        \
    asm volatile(                                                                \
        "mma.sync.aligned.m16n8k16.row.col.f32.bf16.bf16.f32 "                   \
        "{%0,%1,%2,%3},{%4,%5,%6,%7},{%8,%9},{%0,%1,%2,%3};"                     \
        : "+f"((d)[0]), "+f"((d)[1]), "+f"((d)[2]), "+f"((d)[3])                 \
        : "r"((a)[0]), "r"((a)[1]), "r"((a)[2]), "r"((a)[3]),                    \
          "r"((b)[0]), "r"((b)[1]))
#define MMATF32(d, a, b)                                                         \
    asm volatile(                                                                \
        "mma.sync.aligned.m16n8k8.row.col.f32.tf32.tf32.f32 "                    \
        "{%0,%1,%2,%3},{%4,%5,%6,%7},{%8,%9},{%0,%1,%2,%3};"                     \
        : "+f"((d)[0]), "+f"((d)[1]), "+f"((d)[2]), "+f"((d)[3])                 \
        : "r"((a)[0]), "r"((a)[1]), "r"((a)[2]), "r"((a)[3]),                    \
          "r"((b)[0]), "r"((b)[1]))

#define CPASYNC16(dst, src)                                                      \
    asm volatile("cp.async.cg.shared.global [%0], [%1], 16;" :: "r"(dst), "l"(src))
#define CPASYNC16Z(dst, src, sz)                                                 \
    asm volatile("cp.async.cg.shared.global [%0], [%1], 16, %2;"                  \
                 :: "r"(dst), "l"(src), "r"(sz))
#define CPCOMMIT() asm volatile("cp.async.commit_group;" ::: "memory")
#define CPWAIT0()  asm volatile("cp.async.wait_group 0;" ::: "memory")
#define CPWAIT1()  asm volatile("cp.async.wait_group 1;" ::: "memory")

#define PSPLIT(ph, pl, va, vb)                                                   \
    {                                                                            \
        __nv_bfloat162 _h = __float22bfloat162_rn(make_float2((va), (vb)));      \
        float _ra = (va) - __bfloat162float(__low2bfloat16(_h));                 \
        float _rb = (vb) - __bfloat162float(__high2bfloat16(_h));                \
        __nv_bfloat162 _l = __float22bfloat162_rn(make_float2(_ra, _rb));        \
        (ph) = *(uint32_t*)&_h;                                                  \
        (pl) = *(uint32_t*)&_l;                                                  \
    }

extern __shared__ char dynsm[];

// ---------------------------------------------------------------------------
// Converters to tf32 fragment-major layouts.
// ---------------------------------------------------------------------------
__global__ __launch_bounds__(256) void conv_a_tf32(const float* __restrict__ x,
                                                   uint32_t* __restrict__ out) {
    int i = (blockIdx.x * 256 + threadIdx.x) * 4;
    float4 v = *(const float4*)(x + i);
    float f[4] = {v.x, v.y, v.z, v.w};
    int r = i >> 10, c = i & 1023;
    int rb = r >> 4, ri = r & 15, kb = c >> 3;
    int jj = (ri >> 3) + 2 * ((c & 7) >> 2);
    uint32_t* o = out + ((size_t)(rb * 128 + kb) << 7) + jj;
    int lane0 = (ri & 7) * 4;
#pragma unroll
    for (int m = 0; m < 4; m++) o[(lane0 + m) << 2] = f2tf32(f[m]);
}

__global__ __launch_bounds__(256) void conv_b_tf32(const float* __restrict__ w0,
                                                   const float* __restrict__ w1,
                                                   const float* __restrict__ w2,
                                                   const float* __restrict__ w3,
                                                   uint32_t* __restrict__ out) {
    const int z = blockIdx.y;
    const float* w = (z == 0) ? w0 : (z == 1) ? w1 : (z == 2) ? w2 : w3;
    uint32_t* ob = out + (size_t)z * DD * DD;
    int i = (blockIdx.x * 256 + threadIdx.x) * 4;
    float4 v = *(const float4*)(w + i);
    float f[4] = {v.x, v.y, v.z, v.w};
    int n = i >> 10, k = i & 1023;
    int nb = n >> 3, ni = n & 7, kb = k >> 3;
    int j = (k & 7) >> 2;
    uint32_t* o = ob + ((size_t)(nb * 128 + kb) << 6) + j;
    int lane0 = ni * 4;
#pragma unroll
    for (int m = 0; m < 4; m++) o[(lane0 + m) << 1] = f2tf32(f[m]);
}

// ---------------------------------------------------------------------------
// tf32 GEMM mainloop (shared by both epilogues).
// ---------------------------------------------------------------------------
#define T32_STAGE 32768

__device__ __forceinline__ void tf32_mainloop(const uint32_t* A0, const uint32_t* B0,
                                              uint32_t sb, int t, int lane,
                                              int warp_m, int warp_n,
                                              float acc[4][4][4]) {
    auto load_stage = [&](int s, int buf) {
        const int kb0 = s * 4;
        const uint32_t base = sb + buf * T32_STAGE;
#pragma unroll
        for (int it = 0; it < 4; it++) {
            int c = t + it * 256;
            const uint32_t* ga = A0 +
                ((size_t)(((c >> 7) << 7) + kb0 + ((c >> 5) & 3)) << 7) + ((c & 31) << 2);
            CPASYNC16(base + c * 16, ga);
            const uint32_t* gb = B0 +
                ((size_t)(((c >> 6) << 7) + kb0 + ((c >> 4) & 3)) << 6) + ((c & 15) << 2);
            CPASYNC16(base + 16384 + c * 16, gb);
        }
    };

    load_stage(0, 0); CPCOMMIT();
    load_stage(1, 1); CPCOMMIT();

    for (int s = 0; s < 32; s++) {
        CPWAIT1();
        __syncthreads();
        if (s + 2 < 32) load_stage(s + 2, (s + 2) % 3);
        CPCOMMIT();

        const uint32_t sA = sb + (s % 3) * T32_STAGE;
        const uint32_t sB = sA + 16384;

        uint32_t bf[4][4][2];
#pragma unroll
        for (int ks = 0; ks < 4; ks++)
#pragma unroll
            for (int nf = 0; nf < 4; nf++)
                LDS64U(bf[ks][nf],
                       sB + ((((warp_n * 4 + nf) << 2) + ks) << 8) + lane * 8);

        uint32_t ap[2][4];
        LDS128U(ap[0], sA + (((warp_m * 4) << 2) << 9) + lane * 16);
#pragma unroll
        for (int it = 0; it < 16; it++) {
            const int mf = it >> 2, ks = it & 3;
            if (it < 15) {
                const int nmf = (it + 1) >> 2, nks = (it + 1) & 3;
                LDS128U(ap[(it + 1) & 1],
                        sA + ((((warp_m * 4 + nmf) << 2) + nks) << 9) + lane * 16);
            }
#pragma unroll
            for (int nf = 0; nf < 4; nf++)
                MMATF32(acc[mf][nf], ap[it & 1], bf[ks][nf]);
        }
    }
}

// QKV: split-bf16 epilogue (Q scaled by 0.125)
__global__ __launch_bounds__(256, 2)
void tgemm32(const uint32_t* __restrict__ At, const uint32_t* __restrict__ Wt,
             __nv_bfloat16* __restrict__ Ch0, __nv_bfloat16* __restrict__ Cl0,
             __nv_bfloat16* __restrict__ Ch1, __nv_bfloat16* __restrict__ Cl1,
             __nv_bfloat16* __restrict__ Ch2, __nv_bfloat16* __restrict__ Cl2) {
    const int t = threadIdx.x;
    const int lane = t & 31;
    const int wid = t >> 5;
    const int warp_m = wid >> 2, warp_n = wid & 3;
    const int z = blockIdx.z;
    const uint32_t sb = smem_u32(dynsm);

    const uint32_t* A0 = At + ((size_t)(blockIdx.y * 8) << 14);
    const uint32_t* B0 = Wt + (size_t)z * DD * DD + ((size_t)(blockIdx.x * 16) << 13);

    float acc[4][4][4];
#pragma unroll
    for (int i = 0; i < 4; i++)
#pragma unroll
        for (int j = 0; j < 4; j++)
#pragma unroll
            for (int r = 0; r < 4; r++) acc[i][j][r] = 0.f;

    tf32_mainloop(A0, B0, sb, t, lane, warp_m, warp_n, acc);

    __nv_bfloat16* Ch = (z == 0) ? Ch0 : (z == 1) ? Ch1 : Ch2;
    __nv_bfloat16* Cl = (z == 0) ? Cl0 : (z == 1) ? Cl1 : Cl2;
    const float scale = (z == 0) ? 0.125f : 1.0f;
    const int bm = blockIdx.y << 7, bn = blockIdx.x << 7;
#pragma unroll
    for (int mf = 0; mf < 4; mf++) {
        const int r0 = bm + warp_m * 64 + mf * 16 + (lane >> 2);
#pragma unroll
        for (int nf = 0; nf < 4; nf++) {
            const int cn = bn + warp_n * 32 + nf * 8 + (lane & 3) * 2;
#pragma unroll
            for (int hh = 0; hh < 2; hh++) {
                float v0 = acc[mf][nf][hh * 2 + 0] * scale;
                float v1 = acc[mf][nf][hh * 2 + 1] * scale;
                uint32_t ph, pl;
                PSPLIT(ph, pl, v0, v1);
                size_t off = (size_t)(r0 + hh * 8) * DD + cn;
                *(uint32_t*)&Ch[off] = ph;
                *(uint32_t*)&Cl[off] = pl;
            }
        }
    }
}

// O projection: fp32 epilogue
__global__ __launch_bounds__(256, 2)
void tgemm32f(const uint32_t* __restrict__ At, const uint32_t* __restrict__ Wt,
              float* __restrict__ C) {
    const int t = threadIdx.x;
    const int lane = t & 31;
    const int wid = t >> 5;
    const int warp_m = wid >> 2, warp_n = wid & 3;
    const uint32_t sb = smem_u32(dynsm);

    const uint32_t* A0 = At + ((size_t)(blockIdx.y * 8) << 14);
    const uint32_t* B0 = Wt + ((size_t)(blockIdx.x * 16) << 13);

    float acc[4][4][4];
#pragma unroll
    for (int i = 0; i < 4; i++)
#pragma unroll
        for (int j = 0; j < 4; j++)
#pragma unroll
            for (int r = 0; r < 4; r++) acc[i][j][r] = 0.f;

    tf32_mainloop(A0, B0, sb, t, lane, warp_m, warp_n, acc);

    const int bm = blockIdx.y << 7, bn = blockIdx.x << 7;
#pragma unroll
    for (int mf = 0; mf < 4; mf++) {
        const int r0 = bm + warp_m * 64 + mf * 16 + (lane >> 2);
#pragma unroll
        for (int nf = 0; nf < 4; nf++) {
            const int cn = bn + warp_n * 32 + nf * 8 + (lane & 3) * 2;
            *(float2*)&C[(size_t)r0 * DD + cn] =
                make_float2(acc[mf][nf][0], acc[mf][nf][1]);
            *(float2*)&C[(size_t)(r0 + 8) * DD + cn] =
                make_float2(acc[mf][nf][2], acc[mf][nf][3]);
        }
    }
}

// ---------------------------------------------------------------------------
// Tensor-core sliding-window flash attention; fp32 output.
// ---------------------------------------------------------------------------
#define APITCH 144
#define ATILE (64 * APITCH)
#define ABUF  (4 * ATILE)

__global__ __launch_bounds__(256, 1)
void swa_mma(const __nv_bfloat16* __restrict__ Qh, const __nv_bfloat16* __restrict__ Ql,
             const __nv_bfloat16* __restrict__ Kh, const __nv_bfloat16* __restrict__ Kl,
             const __nv_bfloat16* __restrict__ Vh, const __nv_bfloat16* __restrict__ Vl,
             float* __restrict__ O) {
    const int jq = blockIdx.x, h = blockIdx.y, b = blockIdx.z;
    const int t = threadIdx.x, lane = t & 31, wid = t >> 5;
    const int tq = wid * 16;
    const uint32_t sb = smem_u32(dynsm);
    const int kv0 = 128 * jq - 256;

    uint32_t qA[2][4][4];
    {
        const int r0 = 128 * jq + tq + (lane >> 2);
        const size_t rowb = (size_t)(b * SS + r0) * DD + h * DH + 2 * (lane & 3);
        const __nv_bfloat16* Qs[2] = {Qh, Ql};
#pragma unroll
        for (int term = 0; term < 2; term++)
#pragma unroll
            for (int kf = 0; kf < 4; kf++) {
                qA[term][kf][0] = *(const uint32_t*)(Qs[term] + rowb + kf * 16);
                qA[term][kf][1] = *(const uint32_t*)(Qs[term] + rowb + 8 * DD + kf * 16);
                qA[term][kf][2] = *(const uint32_t*)(Qs[term] + rowb + kf * 16 + 8);
                qA[term][kf][3] = *(const uint32_t*)(Qs[term] + rowb + 8 * DD + kf * 16 + 8);
            }
    }

    const __nv_bfloat16* srcs[4] = {Kh, Kl, Vh, Vl};
    auto load_chunk = [&](int c, int buf) {
        const int kbase = kv0 + 64 * c;
#pragma unroll
        for (int it = 0; it < 8; it++) {
            int idx = t + it * 256;
            int tensor = idx >> 9;
            int row = (idx >> 3) & 63;
            int dch = idx & 7;
            int kp = kbase + row;
            int ok = (kp >= 0) ? 16 : 0;
            int kpc = kp >= 0 ? kp : 0;
            uint32_t dst = sb + buf * ABUF + tensor * ATILE + row * APITCH + dch * 16;
            const void* src = srcs[tensor] + (size_t)(b * SS + kpc) * DD + h * DH + dch * 8;
            CPASYNC16Z(dst, src, ok);
        }
    };

    float o[8][4];
#pragma unroll
    for (int nf = 0; nf < 8; nf++)
#pragma unroll
        for (int r = 0; r < 4; r++) o[nf][r] = 0.f;
    float m0 = -1e30f, m1 = -1e30f, lp0 = 0.f, lp1 = 0.f;

    const int cmin = (tq + 1) >> 6;
    const int cmax = (tq + 271) >> 6;

    load_chunk(0, 0);
    CPCOMMIT();

    for (int c = 0; c < 6; c++) {
        if (c < 5) {
            load_chunk(c + 1, (c + 1) & 1);
            CPCOMMIT();
            CPWAIT1();
        } else {
            CPWAIT0();
        }
        __syncthreads();

        const int kbase = kv0 + 64 * c;
        if (c >= cmin && c <= cmax && kbase + 63 >= 0) {
            const uint32_t kvb = sb + (c & 1) * ABUF;

            float s[8][4];
#pragma unroll
            for (int nf = 0; nf < 8; nf++)
#pragma unroll
                for (int r = 0; r < 4; r++) s[nf][r] = 0.f;

#pragma unroll
            for (int kf = 0; kf < 4; kf++) {
#pragma unroll
                for (int kg = 0; kg < 4; kg++) {
                    uint32_t addr = kvb +
                        (kg * 16 + (lane & 7) + ((lane >> 4) << 3)) * APITCH +
                        ((lane >> 3) & 1) * 16 + kf * 32;
                    uint32_t bh[4], bl[4];
                    LDSM4(bh[0], bh[1], bh[2], bh[3], addr);
                    LDSM4(bl[0], bl[1], bl[2], bl[3], addr + ATILE);
                    MMA16816(s[2 * kg],     qA[0][kf], &bh[0]);
                    MMA16816(s[2 * kg],     qA[0][kf], &bl[0]);
                    MMA16816(s[2 * kg],     qA[1][kf], &bh[0]);
                    MMA16816(s[2 * kg + 1], qA[0][kf], &bh[2]);
                    MMA16816(s[2 * kg + 1], qA[0][kf], &bl[2]);
                    MMA16816(s[2 * kg + 1], qA[1][kf], &bh[2]);
                }
            }

            {
                const int qg = 128 * jq + tq + (lane >> 2);
                const int d0 = qg - (kbase + 2 * (lane & 3));
#pragma unroll
                for (int nf = 0; nf < 8; nf++) {
                    int e = d0 - nf * 8;
                    s[nf][0] = ((unsigned)e <= 255u)       ? s[nf][0] : -1e30f;
                    s[nf][1] = ((unsigned)(e - 1) <= 255u) ? s[nf][1] : -1e30f;
                    s[nf][2] = ((unsigned)(e + 8) <= 255u) ? s[nf][2] : -1e30f;
                    s[nf][3] = ((unsigned)(e + 7) <= 255u) ? s[nf][3] : -1e30f;
                }
            }

            float mx0 = -1e30f, mx1 = -1e30f;
#pragma unroll
            for (int nf = 0; nf < 8; nf++) {
                mx0 = fmaxf(mx0, fmaxf(s[nf][0], s[nf][1]));
                mx1 = fmaxf(mx1, fmaxf(s[nf][2], s[nf][3]));
            }
            mx0 = fmaxf(mx0, __shfl_xor_sync(0xffffffffu, mx0, 1));
            mx0 = fmaxf(mx0, __shfl_xor_sync(0xffffffffu, mx0, 2));
            mx1 = fmaxf(mx1, __shfl_xor_sync(0xffffffffu, mx1, 1));
            mx1 = fmaxf(mx1, __shfl_xor_sync(0xffffffffu, mx1, 2));

            float mn0 = fmaxf(m0, mx0), mn1 = fmaxf(m1, mx1);
            float c0 = __expf(m0 - mn0), c1 = __expf(m1 - mn1);
            m0 = mn0; m1 = mn1;

            float ls0 = 0.f, ls1 = 0.f;
#pragma unroll
            for (int nf = 0; nf < 8; nf++) {
                s[nf][0] = __expf(s[nf][0] - mn0);
                s[nf][1] = __expf(s[nf][1] - mn0);
                s[nf][2] = __expf(s[nf][2] - mn1);
                s[nf][3] = __expf(s[nf][3] - mn1);
                ls0 += s[nf][0] + s[nf][1];
                ls1 += s[nf][2] + s[nf][3];
            }
            lp0 = lp0 * c0 + ls0;
            lp1 = lp1 * c1 + ls1;
#pragma unroll
            for (int nf = 0; nf < 8; nf++) {
                o[nf][0] *= c0; o[nf][1] *= c0;
                o[nf][2] *= c1; o[nf][3] *= c1;
            }

#pragma unroll
            for (int kf = 0; kf < 4; kf++) {
                uint32_t pha[4], pla[4];
                PSPLIT(pha[0], pla[0], s[2 * kf][0], s[2 * kf][1]);
                PSPLIT(pha[1], pla[1], s[2 * kf][2], s[2 * kf][3]);
                PSPLIT(pha[2], pla[2], s[2 * kf + 1][0], s[2 * kf + 1][1]);
                PSPLIT(pha[3], pla[3], s[2 * kf + 1][2], s[2 * kf + 1][3]);
#pragma unroll
                for (int dg = 0; dg < 4; dg++) {
                    uint32_t vaddr = kvb + 2 * ATILE +
                        (kf * 16 + (lane & 15)) * APITCH + dg * 32 +
                        ((lane >> 4) & 1) * 16;
                    uint32_t vh4[4], vl4[4];
                    LDSM4T(vh4[0], vh4[1], vh4[2], vh4[3], vaddr);
                    LDSM4T(vl4[0], vl4[1], vl4[2], vl4[3], vaddr + ATILE);
                    MMA16816(o[2 * dg],     pha, &vh4[0]);
                    MMA16816(o[2 * dg],     pha, &vl4[0]);
                    MMA16816(o[2 * dg],     pla, &vh4[0]);
                    MMA16816(o[2 * dg + 1], pha, &vh4[2]);
                    MMA16816(o[2 * dg + 1], pha, &vl4[2]);
                    MMA16816(o[2 * dg + 1], pla, &vh4[2]);
                }
            }
        }
        __syncthreads();
    }

    lp0 += __shfl_xor_sync(0xffffffffu, lp0, 1);
    lp0 += __shfl_xor_sync(0xffffffffu, lp0, 2);
    lp1 += __shfl_xor_sync(0xffffffffu, lp1, 1);
    lp1 += __shfl_xor_sync(0xffffffffu, lp1, 2);
    const float inv0 = 1.f / lp0, inv1 = 1.f / lp1;

    const int r0 = 128 * jq + tq + (lane >> 2);
    const size_t ob = (size_t)(b * SS + r0) * DD + h * DH + 2 * (lane & 3);
#pragma unroll
    for (int nf = 0; nf < 8; nf++) {
        *(float2*)&O[ob + nf * 8] = make_float2(o[nf][0] * inv0, o[nf][1] * inv0);
        *(float2*)&O[ob + 8 * DD + nf * 8] = make_float2(o[nf][2] * inv1, o[nf][3] * inv1);
    }
}

// ---------------------------------------------------------------------------
extern "C" void kernel_launch(void* const* d_in, const int* in_sizes, int n_in,
                              void* d_out, int out_size) {
    const float* x = (const float*)d_in[0];
    const float* w[4] = {(const float*)d_in[1], (const float*)d_in[2],
                         (const float*)d_in[3], (const float*)d_in[4]};
    float* out = (float*)d_out;

    uint32_t *xt, *wt;
    float* ao;
    __nv_bfloat16 *qh, *ql, *kh, *kl, *vh, *vl;
    cudaGetSymbolAddress((void**)&xt, g_xt);
    cudaGetSymbolAddress((void**)&wt, g_wt);
    cudaGetSymbolAddress((void**)&ao, g_ao);
    cudaGetSymbolAddress((void**)&qh, g_qh);
    cudaGetSymbolAddress((void**)&ql, g_ql);
    cudaGetSymbolAddress((void**)&kh, g_kh);
    cudaGetSymbolAddress((void**)&kl, g_kl);
    cudaGetSymbolAddress((void**)&vh, g_vh);
    cudaGetSymbolAddress((void**)&vl, g_vl);

    const int DYNSM_T = 3 * T32_STAGE;    // 98304
    const int DYNSM_A = 2 * ABUF;         // 73728
    cudaFuncSetAttribute(tgemm32,  cudaFuncAttributeMaxDynamicSharedMemorySize, DYNSM_T);
    cudaFuncSetAttribute(tgemm32f, cudaFuncAttributeMaxDynamicSharedMemorySize, DYNSM_T);
    cudaFuncSetAttribute(swa_mma,  cudaFuncAttributeMaxDynamicSharedMemorySize, DYNSM_A);

    conv_a_tf32<<<(MM * DD) / 1024, 256>>>(x, xt);
    conv_b_tf32<<<dim3((DD * DD) / 1024, 4), 256>>>(w[0], w[1], w[2], w[3], wt);

    dim3 gq(DD / 128, MM / 128, 3);   // (8, 64, 3)
    tgemm32<<<gq, 256, DYNSM_T>>>(xt, wt, qh, ql, kh, kl, vh, vl);

    dim3 ga(SS / 128, HH, BB);        // (32, 16, 2)
    swa_mma<<<ga, 256, DYNSM_A>>>(qh, ql, kh, kl, vh, vl, ao);

    // reuse xt for ao in fragment-major tf32 (x is dead after QKV GEMM)
    conv_a_tf32<<<(MM * DD) / 1024, 256>>>(ao, xt);

    dim3 go(DD / 128, MM / 128);      // (8, 64)
    tgemm32f<<<go, 256, DYNSM_T>>>(xt, wt + 3 * (size_t)DD * DD, out);
}

// round 8
// speedup vs baseline: 4.4406x; 1.0178x over previous
#include <cuda_runtime.h>
#include <cuda_bf16.h>
#include <math.h>
#include <stdint.h>

#define BB 2
#define SS 4096
#define DD 1024
#define HH 16
#define DH 64
#define WW 256
#define MM (BB * SS)

// ---------------- device scratch (allocation-free rule) ----------------
__device__ uint32_t g_xt[MM * DD];          // x (then ao) in tf32, A-fragment-major
__device__ uint32_t g_wt[4 * DD * DD];      // wq,wk,wv,wo in tf32, B-fragment-major
__device__ float g_ao[MM * DD];             // attention output, fp32
__device__ __nv_bfloat16 g_qh[MM * DD];
__device__ __nv_bfloat16 g_ql[MM * DD];
__device__ __nv_bfloat16 g_kh[MM * DD];
__device__ __nv_bfloat16 g_kl[MM * DD];
__device__ __nv_bfloat16 g_vh[MM * DD];
__device__ __nv_bfloat16 g_vl[MM * DD];

// ---------------- family-portable PTX helpers ----------------
__device__ __forceinline__ uint32_t smem_u32(const void* p) {
    uint32_t a;
    asm("{ .reg .u64 t; cvta.to.shared.u64 t, %1; cvt.u32.u64 %0, t; }"
        : "=r"(a) : "l"(p));
    return a;
}
__device__ __forceinline__ uint32_t f2tf32(float f) {
    uint32_t u;
    asm("cvt.rna.tf32.f32 %0, %1;" : "=r"(u) : "f"(f));
    return u;
}

#define LDSM4(r0, r1, r2, r3, addr)                                              \
    asm volatile("ldmatrix.sync.aligned.m8n8.x4.shared.b16 {%0,%1,%2,%3}, [%4];"  \
                 : "=r"(r0), "=r"(r1), "=r"(r2), "=r"(r3) : "r"(addr))
#define LDSM4T(r0, r1, r2, r3, addr)                                             \
    asm volatile("ldmatrix.sync.aligned.m8n8.x4.trans.shared.b16 {%0,%1,%2,%3}, [%4];" \
                 : "=r"(r0), "=r"(r1), "=r"(r2), "=r"(r3) : "r"(addr))
#define LDS128U(r, addr)                                                         \
    asm volatile("ld.shared.v4.b32 {%0,%1,%2,%3}, [%4];"                          \
                 : "=r"((r)[0]), "=r"((r)[1]), "=r"((r)[2]), "=r"((r)[3])         \
                 : "r"(addr))
#define LDS64U(r, addr)                                                          \
    asm volatile("ld.shared.v2.b32 {%0,%1}, [%2];"                                \
                 : "=r"((r)[0]), "=r"((r)[1]) : "r"(addr))

#define MMA16816(d, a, b)                                                        \
    asm volatile(                                                                \
        "mma.sync.aligned.m16n8k16.row.col.f32.bf16.bf16.f32 "                   \
        "{%0,%1,%2,%3},{%4,%5,%6,%7},{%8,%9},{%0,%1,%2,%3};"                     \
        : "+f"((d)[0]), "+f"((d)[1]), "+f"((d)[2]), "+f"((d)[3])                 \
        : "r"((a)[0]), "r"((a)[1]), "r"((a)[2]), "r"((a)[3]),                    \
          "r"((b)[0]), "r"((b)[1]))
#define MMATF32(d, a, b)                                                         \
    asm volatile(                                                                \
        "mma.sync.aligned.m16n8k8.row.col.f32.tf32.tf32.f32 "                    \
        "{%0,%1,%2,%3},{%4,%5,%6,%7},{%8,%9},{%0,%1,%2,%3};"                     \
        : "+f"((d)[0]), "+f"((d)[1]), "+f"((d)[2]), "+f"((d)[3])                 \
        : "r"((a)[0]), "r"((a)[1]), "r"((a)[2]), "r"((a)[3]),                    \
          "r"((b)[0]), "r"((b)[1]))

#define CPASYNC16Z(dst, src, sz)                                                 \
    asm volatile("cp.async.cg.shared.global [%0], [%1], 16, %2;"                  \
                 :: "r"(dst), "l"(src), "r"(sz))
#define CPCOMMIT() asm volatile("cp.async.commit_group;" ::: "memory")
#define CPWAIT0()  asm volatile("cp.async.wait_group 0;" ::: "memory")
#define CPWAIT1()  asm volatile("cp.async.wait_group 1;" ::: "memory")

// --- bulk async copy + mbarrier (sm_90 baseline, family-portable) ---
#define MBAR_INIT(a, c)                                                          \
    asm volatile("mbarrier.init.shared.b64 [%0], %1;" :: "r"(a), "r"(c) : "memory")
#define MBAR_EXPECT(a, bytes)                                                    \
    asm volatile("mbarrier.arrive.expect_tx.shared.b64 _, [%0], %1;"              \
                 :: "r"(a), "r"(bytes) : "memory")
#define BULKCP(dst, src, sz, mb)                                                 \
    asm volatile("cp.async.bulk.shared::cta.global.mbarrier::complete_tx::bytes " \
                 "[%0], [%1], %2, [%3];"                                          \
                 :: "r"(dst), "l"(src), "r"(sz), "r"(mb) : "memory")
#define MBAR_WAIT(a, p)                                                          \
    asm volatile(                                                                \
        "{\n\t.reg .pred P;\n\t"                                                 \
        "W_%=:\n\t"                                                              \
        "mbarrier.try_wait.parity.acquire.cta.shared::cta.b64 P, [%0], %1;\n\t"  \
        "@P bra.uni D_%=;\n\t"                                                   \
        "bra.uni W_%=;\n\t"                                                      \
        "D_%=:\n\t}"                                                             \
        :: "r"(a), "r"(p) : "memory")

#define PSPLIT(ph, pl, va, vb)                                                   \
    {                                                                            \
        __nv_bfloat162 _h = __float22bfloat162_rn(make_float2((va), (vb)));      \
        float _ra = (va) - __bfloat162float(__low2bfloat16(_h));                 \
        float _rb = (vb) - __bfloat162float(__high2bfloat16(_h));                \
        __nv_bfloat162 _l = __float22bfloat162_rn(make_float2(_ra, _rb));        \
        (ph) = *(uint32_t*)&_h;                                                  \
        (pl) = *(uint32_t*)&_l;                                                  \
    }

extern __shared__ char dynsm[];

// ---------------------------------------------------------------------------
// Converters to tf32 fragment-major layouts.
// ---------------------------------------------------------------------------
__global__ __launch_bounds__(256) void conv_a_tf32(const float* __restrict__ x,
                                                   uint32_t* __restrict__ out) {
    int i = (blockIdx.x * 256 + threadIdx.x) * 4;
    float4 v = *(const float4*)(x + i);
    float f[4] = {v.x, v.y, v.z, v.w};
    int r = i >> 10, c = i & 1023;
    int rb = r >> 4, ri = r & 15, kb = c >> 3;
    int jj = (ri >> 3) + 2 * ((c & 7) >> 2);
    uint32_t* o = out + ((size_t)(rb * 128 + kb) << 7) + jj;
    int lane0 = (ri & 7) * 4;
#pragma unroll
    for (int m = 0; m < 4; m++) o[(lane0 + m) << 2] = f2tf32(f[m]);
}

__global__ __launch_bounds__(256) void conv_b_tf32(const float* __restrict__ w0,
                                                   const float* __restrict__ w1,
                                                   const float* __restrict__ w2,
                                                   const float* __restrict__ w3,
                                                   uint32_t* __restrict__ out) {
    const int z = blockIdx.y;
    const float* w = (z == 0) ? w0 : (z == 1) ? w1 : (z == 2) ? w2 : w3;
    uint32_t* ob = out + (size_t)z * DD * DD;
    int i = (blockIdx.x * 256 + threadIdx.x) * 4;
    float4 v = *(const float4*)(w + i);
    float f[4] = {v.x, v.y, v.z, v.w};
    int n = i >> 10, k = i & 1023;
    int nb = n >> 3, ni = n & 7, kb = k >> 3;
    int j = (k & 7) >> 2;
    uint32_t* o = ob + ((size_t)(nb * 128 + kb) << 6) + j;
    int lane0 = ni * 4;
#pragma unroll
    for (int m = 0; m < 4; m++) o[(lane0 + m) << 1] = f2tf32(f[m]);
}

// ---------------------------------------------------------------------------
// tf32 GEMM mainloop: 128x128 tile, BK=32, 3-stage ring staged by
// cp.async.bulk + mbarrier (24 bulk copies/stage issued by thread 0).
// ---------------------------------------------------------------------------
#define T32_STAGE 32768

__device__ __forceinline__ void tf32_mainloop(const uint32_t* A0, const uint32_t* B0,
                                              uint32_t sb, int t, int lane,
                                              int warp_m, int warp_n,
                                              float acc[4][4][4]) {
    __shared__ __align__(8) unsigned long long mbars[3];
    const uint32_t mb = smem_u32(mbars);

    if (t == 0) {
        MBAR_INIT(mb + 0, 1);
        MBAR_INIT(mb + 8, 1);
        MBAR_INIT(mb + 16, 1);
    }
    __syncthreads();

    auto issue = [&](int s, int buf) {
        const uint32_t base = sb + buf * T32_STAGE;
        const uint32_t m = mb + buf * 8;
        const int kb0 = s * 4;
        MBAR_EXPECT(m, 32768u);
#pragma unroll
        for (int rbl = 0; rbl < 8; rbl++)
            BULKCP(base + rbl * 2048, A0 + (((rbl << 7) + kb0) << 7), 2048u, m);
#pragma unroll
        for (int nbl = 0; nbl < 16; nbl++)
            BULKCP(base + 16384 + nbl * 1024, B0 + (((nbl << 7) + kb0) << 6), 1024u, m);
    };

    if (t == 0) { issue(0, 0); issue(1, 1); }

    for (int s = 0; s < 32; s++) {
        const int buf = s - (s / 3) * 3;          // s % 3
        const int par = (s / 3) & 1;
        MBAR_WAIT(mb + buf * 8, par);
        __syncthreads();                          // all warps done reading buf (s+2)%3
        if (t == 0 && s + 2 < 32) issue(s + 2, (s + 2) % 3);

        const uint32_t sA = sb + buf * T32_STAGE;
        const uint32_t sB = sA + 16384;

        uint32_t bf[4][4][2];
#pragma unroll
        for (int ks = 0; ks < 4; ks++)
#pragma unroll
            for (int nf = 0; nf < 4; nf++)
                LDS64U(bf[ks][nf],
                       sB + ((((warp_n * 4 + nf) << 2) + ks) << 8) + lane * 8);

        uint32_t ap[2][4];
        LDS128U(ap[0], sA + (((warp_m * 4) << 2) << 9) + lane * 16);
#pragma unroll
        for (int it = 0; it < 16; it++) {
            const int mf = it >> 2, ks = it & 3;
            if (it < 15) {
                const int nmf = (it + 1) >> 2, nks = (it + 1) & 3;
                LDS128U(ap[(it + 1) & 1],
                        sA + ((((warp_m * 4 + nmf) << 2) + nks) << 9) + lane * 16);
            }
#pragma unroll
            for (int nf = 0; nf < 4; nf++)
                MMATF32(acc[mf][nf], ap[it & 1], bf[ks][nf]);
        }
    }
}

// QKV: split-bf16 epilogue (Q scaled by 0.125)
__global__ __launch_bounds__(256, 2)
void tgemm32(const uint32_t* __restrict__ At, const uint32_t* __restrict__ Wt,
             __nv_bfloat16* __restrict__ Ch0, __nv_bfloat16* __restrict__ Cl0,
             __nv_bfloat16* __restrict__ Ch1, __nv_bfloat16* __restrict__ Cl1,
             __nv_bfloat16* __restrict__ Ch2, __nv_bfloat16* __restrict__ Cl2) {
    const int t = threadIdx.x;
    const int lane = t & 31;
    const int wid = t >> 5;
    const int warp_m = wid >> 2, warp_n = wid & 3;
    const int z = blockIdx.z;
    const uint32_t sb = smem_u32(dynsm);

    const uint32_t* A0 = At + ((size_t)(blockIdx.y * 8) << 14);
    const uint32_t* B0 = Wt + (size_t)z * DD * DD + ((size_t)(blockIdx.x * 16) << 13);

    float acc[4][4][4];
#pragma unroll
    for (int i = 0; i < 4; i++)
#pragma unroll
        for (int j = 0; j < 4; j++)
#pragma unroll
            for (int r = 0; r < 4; r++) acc[i][j][r] = 0.f;

    tf32_mainloop(A0, B0, sb, t, lane, warp_m, warp_n, acc);

    __nv_bfloat16* Ch = (z == 0) ? Ch0 : (z == 1) ? Ch1 : Ch2;
    __nv_bfloat16* Cl = (z == 0) ? Cl0 : (z == 1) ? Cl1 : Cl2;
    const float scale = (z == 0) ? 0.125f : 1.0f;
    const int bm = blockIdx.y << 7, bn = blockIdx.x << 7;
#pragma unroll
    for (int mf = 0; mf < 4; mf++) {
        const int r0 = bm + warp_m * 64 + mf * 16 + (lane >> 2);
#pragma unroll
        for (int nf = 0; nf < 4; nf++) {
            const int cn = bn + warp_n * 32 + nf * 8 + (lane & 3) * 2;
#pragma unroll
            for (int hh = 0; hh < 2; hh++) {
                float v0 = acc[mf][nf][hh * 2 + 0] * scale;
                float v1 = acc[mf][nf][hh * 2 + 1] * scale;
                uint32_t ph, pl;
                PSPLIT(ph, pl, v0, v1);
                size_t off = (size_t)(r0 + hh * 8) * DD + cn;
                *(uint32_t*)&Ch[off] = ph;
                *(uint32_t*)&Cl[off] = pl;
            }
        }
    }
}

// O projection: fp32 epilogue
__global__ __launch_bounds__(256, 2)
void tgemm32f(const uint32_t* __restrict__ At, const uint32_t* __restrict__ Wt,
              float* __restrict__ C) {
    const int t = threadIdx.x;
    const int lane = t & 31;
    const int wid = t >> 5;
    const int warp_m = wid >> 2, warp_n = wid & 3;
    const uint32_t sb = smem_u32(dynsm);

    const uint32_t* A0 = At + ((size_t)(blockIdx.y * 8) << 14);
    const uint32_t* B0 = Wt + ((size_t)(blockIdx.x * 16) << 13);

    float acc[4][4][4];
#pragma unroll
    for (int i = 0; i < 4; i++)
#pragma unroll
        for (int j = 0; j < 4; j++)
#pragma unroll
            for (int r = 0; r < 4; r++) acc[i][j][r] = 0.f;

    tf32_mainloop(A0, B0, sb, t, lane, warp_m, warp_n, acc);

    const int bm = blockIdx.y << 7, bn = blockIdx.x << 7;
#pragma unroll
    for (int mf = 0; mf < 4; mf++) {
        const int r0 = bm + warp_m * 64 + mf * 16 + (lane >> 2);
#pragma unroll
        for (int nf = 0; nf < 4; nf++) {
            const int cn = bn + warp_n * 32 + nf * 8 + (lane & 3) * 2;
            *(float2*)&C[(size_t)r0 * DD + cn] =
                make_float2(acc[mf][nf][0], acc[mf][nf][1]);
            *(float2*)&C[(size_t)(r0 + 8) * DD + cn] =
                make_float2(acc[mf][nf][2], acc[mf][nf][3]);
        }
    }
}

// ---------------------------------------------------------------------------
// Tensor-core sliding-window flash attention; fp32 output. (unchanged)
// ---------------------------------------------------------------------------
#define APITCH 144
#define ATILE (64 * APITCH)
#define ABUF  (4 * ATILE)

__global__ __launch_bounds__(256, 1)
void swa_mma(const __nv_bfloat16* __restrict__ Qh, const __nv_bfloat16* __restrict__ Ql,
             const __nv_bfloat16* __restrict__ Kh, const __nv_bfloat16* __restrict__ Kl,
             const __nv_bfloat16* __restrict__ Vh, const __nv_bfloat16* __restrict__ Vl,
             float* __restrict__ O) {
    const int jq = blockIdx.x, h = blockIdx.y, b = blockIdx.z;
    const int t = threadIdx.x, lane = t & 31, wid = t >> 5;
    const int tq = wid * 16;
    const uint32_t sb = smem_u32(dynsm);
    const int kv0 = 128 * jq - 256;

    uint32_t qA[2][4][4];
    {
        const int r0 = 128 * jq + tq + (lane >> 2);
        const size_t rowb = (size_t)(b * SS + r0) * DD + h * DH + 2 * (lane & 3);
        const __nv_bfloat16* Qs[2] = {Qh, Ql};
#pragma unroll
        for (int term = 0; term < 2; term++)
#pragma unroll
            for (int kf = 0; kf < 4; kf++) {
                qA[term][kf][0] = *(const uint32_t*)(Qs[term] + rowb + kf * 16);
                qA[term][kf][1] = *(const uint32_t*)(Qs[term] + rowb + 8 * DD + kf * 16);
                qA[term][kf][2] = *(const uint32_t*)(Qs[term] + rowb + kf * 16 + 8);
                qA[term][kf][3] = *(const uint32_t*)(Qs[term] + rowb + 8 * DD + kf * 16 + 8);
            }
    }

    const __nv_bfloat16* srcs[4] = {Kh, Kl, Vh, Vl};
    auto load_chunk = [&](int c, int buf) {
        const int kbase = kv0 + 64 * c;
#pragma unroll
        for (int it = 0; it < 8; it++) {
            int idx = t + it * 256;
            int tensor = idx >> 9;
            int row = (idx >> 3) & 63;
            int dch = idx & 7;
            int kp = kbase + row;
            int ok = (kp >= 0) ? 16 : 0;
            int kpc = kp >= 0 ? kp : 0;
            uint32_t dst = sb + buf * ABUF + tensor * ATILE + row * APITCH + dch * 16;
            const void* src = srcs[tensor] + (size_t)(b * SS + kpc) * DD + h * DH + dch * 8;
            CPASYNC16Z(dst, src, ok);
        }
    };

    float o[8][4];
#pragma unroll
    for (int nf = 0; nf < 8; nf++)
#pragma unroll
        for (int r = 0; r < 4; r++) o[nf][r] = 0.f;
    float m0 = -1e30f, m1 = -1e30f, lp0 = 0.f, lp1 = 0.f;

    const int cmin = (tq + 1) >> 6;
    const int cmax = (tq + 271) >> 6;

    load_chunk(0, 0);
    CPCOMMIT();

    for (int c = 0; c < 6; c++) {
        if (c < 5) {
            load_chunk(c + 1, (c + 1) & 1);
            CPCOMMIT();
            CPWAIT1();
        } else {
            CPWAIT0();
        }
        __syncthreads();

        const int kbase = kv0 + 64 * c;
        if (c >= cmin && c <= cmax && kbase + 63 >= 0) {
            const uint32_t kvb = sb + (c & 1) * ABUF;

            float s[8][4];
#pragma unroll
            for (int nf = 0; nf < 8; nf++)
#pragma unroll
                for (int r = 0; r < 4; r++) s[nf][r] = 0.f;

#pragma unroll
            for (int kf = 0; kf < 4; kf++) {
#pragma unroll
                for (int kg = 0; kg < 4; kg++) {
                    uint32_t addr = kvb +
                        (kg * 16 + (lane & 7) + ((lane >> 4) << 3)) * APITCH +
                        ((lane >> 3) & 1) * 16 + kf * 32;
                    uint32_t bh[4], bl[4];
                    LDSM4(bh[0], bh[1], bh[2], bh[3], addr);
                    LDSM4(bl[0], bl[1], bl[2], bl[3], addr + ATILE);
                    MMA16816(s[2 * kg],     qA[0][kf], &bh[0]);
                    MMA16816(s[2 * kg],     qA[0][kf], &bl[0]);
                    MMA16816(s[2 * kg],     qA[1][kf], &bh[0]);
                    MMA16816(s[2 * kg + 1], qA[0][kf], &bh[2]);
                    MMA16816(s[2 * kg + 1], qA[0][kf], &bl[2]);
                    MMA16816(s[2 * kg + 1], qA[1][kf], &bh[2]);
                }
            }

            {
                const int qg = 128 * jq + tq + (lane >> 2);
                const int d0 = qg - (kbase + 2 * (lane & 3));
#pragma unroll
                for (int nf = 0; nf < 8; nf++) {
                    int e = d0 - nf * 8;
                    s[nf][0] = ((unsigned)e <= 255u)       ? s[nf][0] : -1e30f;
                    s[nf][1] = ((unsigned)(e - 1) <= 255u) ? s[nf][1] : -1e30f;
                    s[nf][2] = ((unsigned)(e + 8) <= 255u) ? s[nf][2] : -1e30f;
                    s[nf][3] = ((unsigned)(e + 7) <= 255u) ? s[nf][3] : -1e30f;
                }
            }

            float mx0 = -1e30f, mx1 = -1e30f;
#pragma unroll
            for (int nf = 0; nf < 8; nf++) {
                mx0 = fmaxf(mx0, fmaxf(s[nf][0], s[nf][1]));
                mx1 = fmaxf(mx1, fmaxf(s[nf][2], s[nf][3]));
            }
            mx0 = fmaxf(mx0, __shfl_xor_sync(0xffffffffu, mx0, 1));
            mx0 = fmaxf(mx0, __shfl_xor_sync(0xffffffffu, mx0, 2));
            mx1 = fmaxf(mx1, __shfl_xor_sync(0xffffffffu, mx1, 1));
            mx1 = fmaxf(mx1, __shfl_xor_sync(0xffffffffu, mx1, 2));

            float mn0 = fmaxf(m0, mx0), mn1 = fmaxf(m1, mx1);
            float c0 = __expf(m0 - mn0), c1 = __expf(m1 - mn1);
            m0 = mn0; m1 = mn1;

            float ls0 = 0.f, ls1 = 0.f;
#pragma unroll
            for (int nf = 0; nf < 8; nf++) {
                s[nf][0] = __expf(s[nf][0] - mn0);
                s[nf][1] = __expf(s[nf][1] - mn0);
                s[nf][2] = __expf(s[nf][2] - mn1);
                s[nf][3] = __expf(s[nf][3] - mn1);
                ls0 += s[nf][0] + s[nf][1];
                ls1 += s[nf][2] + s[nf][3];
            }
            lp0 = lp0 * c0 + ls0;
            lp1 = lp1 * c1 + ls1;
#pragma unroll
            for (int nf = 0; nf < 8; nf++) {
                o[nf][0] *= c0; o[nf][1] *= c0;
                o[nf][2] *= c1; o[nf][3] *= c1;
            }

#pragma unroll
            for (int kf = 0; kf < 4; kf++) {
                uint32_t pha[4], pla[4];
                PSPLIT(pha[0], pla[0], s[2 * kf][0], s[2 * kf][1]);
                PSPLIT(pha[1], pla[1], s[2 * kf][2], s[2 * kf][3]);
                PSPLIT(pha[2], pla[2], s[2 * kf + 1][0], s[2 * kf + 1][1]);
                PSPLIT(pha[3], pla[3], s[2 * kf + 1][2], s[2 * kf + 1][3]);
#pragma unroll
                for (int dg = 0; dg < 4; dg++) {
                    uint32_t vaddr = kvb + 2 * ATILE +
                        (kf * 16 + (lane & 15)) * APITCH + dg * 32 +
                        ((lane >> 4) & 1) * 16;
                    uint32_t vh4[4], vl4[4];
                    LDSM4T(vh4[0], vh4[1], vh4[2], vh4[3], vaddr);
                    LDSM4T(vl4[0], vl4[1], vl4[2], vl4[3], vaddr + ATILE);
                    MMA16816(o[2 * dg],     pha, &vh4[0]);
                    MMA16816(o[2 * dg],     pha, &vl4[0]);
                    MMA16816(o[2 * dg],     pla, &vh4[0]);
                    MMA16816(o[2 * dg + 1], pha, &vh4[2]);
                    MMA16816(o[2 * dg + 1], pha, &vl4[2]);
                    MMA16816(o[2 * dg + 1], pla, &vh4[2]);
                }
            }
        }
        __syncthreads();
    }

    lp0 += __shfl_xor_sync(0xffffffffu, lp0, 1);
    lp0 += __shfl_xor_sync(0xffffffffu, lp0, 2);
    lp1 += __shfl_xor_sync(0xffffffffu, lp1, 1);
    lp1 += __shfl_xor_sync(0xffffffffu, lp1, 2);
    const float inv0 = 1.f / lp0, inv1 = 1.f / lp1;

    const int r0 = 128 * jq + tq + (lane >> 2);
    const size_t ob = (size_t)(b * SS + r0) * DD + h * DH + 2 * (lane & 3);
#pragma unroll
    for (int nf = 0; nf < 8; nf++) {
        *(float2*)&O[ob + nf * 8] = make_float2(o[nf][0] * inv0, o[nf][1] * inv0);
        *(float2*)&O[ob + 8 * DD + nf * 8] = make_float2(o[nf][2] * inv1, o[nf][3] * inv1);
    }
}

// ---------------------------------------------------------------------------
extern "C" void kernel_launch(void* const* d_in, const int* in_sizes, int n_in,
                              void* d_out, int out_size) {
    const float* x = (const float*)d_in[0];
    const float* w[4] = {(const float*)d_in[1], (const float*)d_in[2],
                         (const float*)d_in[3], (const float*)d_in[4]};
    float* out = (float*)d_out;

    uint32_t *xt, *wt;
    float* ao;
    __nv_bfloat16 *qh, *ql, *kh, *kl, *vh, *vl;
    cudaGetSymbolAddress((void**)&xt, g_xt);
    cudaGetSymbolAddress((void**)&wt, g_wt);
    cudaGetSymbolAddress((void**)&ao, g_ao);
    cudaGetSymbolAddress((void**)&qh, g_qh);
    cudaGetSymbolAddress((void**)&ql, g_ql);
    cudaGetSymbolAddress((void**)&kh, g_kh);
    cudaGetSymbolAddress((void**)&kl, g_kl);
    cudaGetSymbolAddress((void**)&vh, g_vh);
    cudaGetSymbolAddress((void**)&vl, g_vl);

    const int DYNSM_T = 3 * T32_STAGE;    // 98304
    const int DYNSM_A = 2 * ABUF;         // 73728
    cudaFuncSetAttribute(tgemm32,  cudaFuncAttributeMaxDynamicSharedMemorySize, DYNSM_T);
    cudaFuncSetAttribute(tgemm32f, cudaFuncAttributeMaxDynamicSharedMemorySize, DYNSM_T);
    cudaFuncSetAttribute(swa_mma,  cudaFuncAttributeMaxDynamicSharedMemorySize, DYNSM_A);

    conv_a_tf32<<<(MM * DD) / 1024, 256>>>(x, xt);
    conv_b_tf32<<<dim3((DD * DD) / 1024, 4), 256>>>(w[0], w[1], w[2], w[3], wt);

    dim3 gq(DD / 128, MM / 128, 3);   // (8, 64, 3)
    tgemm32<<<gq, 256, DYNSM_T>>>(xt, wt, qh, ql, kh, kl, vh, vl);

    dim3 ga(SS / 128, HH, BB);        // (32, 16, 2)
    swa_mma<<<ga, 256, DYNSM_A>>>(qh, ql, kh, kl, vh, vl, ao);

    // reuse xt for ao in fragment-major tf32 (x is dead after QKV GEMM)
    conv_a_tf32<<<(MM * DD) / 1024, 256>>>(ao, xt);

    dim3 go(DD / 128, MM / 128);      // (8, 64)
    tgemm32f<<<go, 256, DYNSM_T>>>(xt, wt + 3 * (size_t)DD * DD, out);
}